// round 1
// baseline (speedup 1.0000x reference)
#include <cuda_runtime.h>
#include <math.h>

#define Bsz 16384
#define Hd  128
#define Cc  4
#define Ll  6
#define NHh 4
#define HDd 32
#define Oo  1024
#define G3H 384

// ---------------- scratch (static device globals; no allocations) ----------
__device__ float g_x0 [(size_t)Bsz * Hd];
__device__ float g_gi [(size_t)Cc * Bsz * G3H];
__device__ float g_gh [(size_t)Cc * Bsz * G3H];
__device__ float g_qkv[(size_t)Cc * Bsz * G3H];
__device__ float g_hn [(size_t)Cc * Bsz * Hd];
__device__ float g_att[(size_t)Cc * Bsz * Hd];
__device__ float g_msg[(size_t)Cc * Bsz * Hd];

__device__ __forceinline__ float sigf(float x) { return 1.0f / (1.0f + expf(-x)); }

// ---------------- generic GEMM: Y[c,b,g] = sum_k X[c,b,k]*W[c,g,k] + bias[c,g]
// K fixed = 128. Tile: 128 (b) x 64 (g), 256 threads, 8x4 microtile.
__global__ __launch_bounds__(256) void gemm_bias(
    const float* __restrict__ X, const float* __restrict__ W,
    const float* __restrict__ bias, float* __restrict__ Y,
    int G, long xStride, long wStride, long bStride, long yStride)
{
    int c = blockIdx.z;
    X    += (long)c * xStride;
    W    += (long)c * wStride;
    bias += (long)c * bStride;
    Y    += (long)c * yStride;

    __shared__ float Xs[16][128];
    __shared__ float Ws[16][64];

    int tid = threadIdx.x;
    int tx = tid & 15;        // 0..15 -> g sub-tile
    int ty = tid >> 4;        // 0..15 -> b sub-tile
    int b0 = blockIdx.x * 128;
    int g0 = blockIdx.y * 64;

    float acc[8][4];
    #pragma unroll
    for (int i = 0; i < 8; i++)
        #pragma unroll
        for (int j = 0; j < 4; j++) acc[i][j] = 0.0f;

    int lr = tid >> 2;            // 0..63
    int lk = (tid & 3) << 2;      // 0,4,8,12

    const float* Xbase = X + (long)b0 * 128;
    const float* Wbase = W + (long)g0 * 128;

    for (int k0 = 0; k0 < 128; k0 += 16) {
        float4 xa = *(const float4*)(Xbase + (long)lr        * 128 + k0 + lk);
        float4 xb = *(const float4*)(Xbase + (long)(lr + 64) * 128 + k0 + lk);
        float4 wv = *(const float4*)(Wbase + (long)lr        * 128 + k0 + lk);
        Xs[lk+0][lr]    = xa.x; Xs[lk+1][lr]    = xa.y; Xs[lk+2][lr]    = xa.z; Xs[lk+3][lr]    = xa.w;
        Xs[lk+0][lr+64] = xb.x; Xs[lk+1][lr+64] = xb.y; Xs[lk+2][lr+64] = xb.z; Xs[lk+3][lr+64] = xb.w;
        Ws[lk+0][lr]    = wv.x; Ws[lk+1][lr]    = wv.y; Ws[lk+2][lr]    = wv.z; Ws[lk+3][lr]    = wv.w;
        __syncthreads();
        #pragma unroll
        for (int kk = 0; kk < 16; kk++) {
            float4 x0v = *(const float4*)&Xs[kk][ty * 8];
            float4 x1v = *(const float4*)&Xs[kk][ty * 8 + 4];
            float4 wf  = *(const float4*)&Ws[kk][tx * 4];
            float xr[8] = {x0v.x, x0v.y, x0v.z, x0v.w, x1v.x, x1v.y, x1v.z, x1v.w};
            float wr[4] = {wf.x, wf.y, wf.z, wf.w};
            #pragma unroll
            for (int i = 0; i < 8; i++)
                #pragma unroll
                for (int j = 0; j < 4; j++)
                    acc[i][j] += xr[i] * wr[j];
        }
        __syncthreads();
    }

    float4 bv = *(const float4*)(bias + g0 + tx * 4);
    #pragma unroll
    for (int i = 0; i < 8; i++) {
        float4 o;
        o.x = acc[i][0] + bv.x;
        o.y = acc[i][1] + bv.y;
        o.z = acc[i][2] + bv.z;
        o.w = acc[i][3] + bv.w;
        *(float4*)(Y + (long)(b0 + ty * 8 + i) * G + g0 + tx * 4) = o;
    }
}

// ---------------- embedding gather: x0[b,:] = emb[tokens[b],:] --------------
__global__ void gather_x0(const int* __restrict__ tok, const float* __restrict__ emb)
{
    long t = (long)blockIdx.x * 256 + threadIdx.x;   // B*32 threads
    int b  = (int)(t >> 5);
    int e4 = (int)(t & 31) << 2;
    float4 v = *(const float4*)(emb + (long)tok[b] * 128 + e4);
    *(float4*)(g_x0 + (long)b * 128 + e4) = v;
}

// ---------------- l=0 cells 1..3: gi = bias broadcast -----------------------
__global__ void fill_gi0(const float* __restrict__ bih0)
{
    long t = (long)blockIdx.x * 256 + threadIdx.x;   // 3*B*96 float4 units
    int  g4  = (int)(t % 96) * 4;
    long rem = t / 96;
    int  b   = (int)(rem % Bsz);
    int  c   = 1 + (int)(rem / Bsz);
    float4 v = *(const float4*)(bih0 + (long)c * G3H + g4);
    *(float4*)(g_gi + ((long)c * Bsz + b) * G3H + g4) = v;
}

// ---------------- GRU elementwise -------------------------------------------
__global__ void gru_kernel(const float* __restrict__ hprev)
{
    long t   = (long)blockIdx.x * 256 + threadIdx.x;   // C*B*32
    long row = t >> 5;
    int  h4  = (int)(t & 31) << 2;
    const float* gi = g_gi + row * G3H;
    const float* gh = g_gh + row * G3H;

    float4 ir  = *(const float4*)(gi + h4);
    float4 iz  = *(const float4*)(gi + 128 + h4);
    float4 inn = *(const float4*)(gi + 256 + h4);
    float4 hr  = *(const float4*)(gh + h4);
    float4 hz  = *(const float4*)(gh + 128 + h4);
    float4 hnn = *(const float4*)(gh + 256 + h4);
    float4 hp  = *(const float4*)(hprev + row * 128 + h4);

    float4 out;
    {
        float r = sigf(ir.x + hr.x), z = sigf(iz.x + hz.x);
        float n = tanhf(inn.x + r * hnn.x);
        out.x = (1.0f - z) * n + z * hp.x;
    }
    {
        float r = sigf(ir.y + hr.y), z = sigf(iz.y + hz.y);
        float n = tanhf(inn.y + r * hnn.y);
        out.y = (1.0f - z) * n + z * hp.y;
    }
    {
        float r = sigf(ir.z + hr.z), z = sigf(iz.z + hz.z);
        float n = tanhf(inn.z + r * hnn.z);
        out.z = (1.0f - z) * n + z * hp.z;
    }
    {
        float r = sigf(ir.w + hr.w), z = sigf(iz.w + hz.w);
        float n = tanhf(inn.w + r * hnn.w);
        out.w = (1.0f - z) * n + z * hp.w;
    }
    *(float4*)(g_hn + row * 128 + h4) = out;
}

// ---------------- tiny attention over C=4 positions --------------------------
__global__ void attn_kernel()
{
    int gw   = blockIdx.x * 4 + (threadIdx.x >> 5);   // (b, nh) index
    int lane = threadIdx.x & 31;                      // = head dim
    int b  = gw >> 2;
    int nh = gw & 3;

    float q[4], k[4], v[4];
    #pragma unroll
    for (int c = 0; c < 4; c++) {
        const float* p = g_qkv + ((long)c * Bsz + b) * G3H + nh * 32 + lane;
        q[c] = p[0];
        k[c] = p[128];
        v[c] = p[256];
    }

    float s[4][4];
    #pragma unroll
    for (int qc = 0; qc < 4; qc++) {
        #pragma unroll
        for (int kc = 0; kc < 4; kc++) {
            float p = q[qc] * k[kc];
            #pragma unroll
            for (int off = 16; off > 0; off >>= 1)
                p += __shfl_xor_sync(0xFFFFFFFFu, p, off);
            s[qc][kc] = p * 0.17677669529663687f;   // 1/sqrt(32)
        }
    }

    #pragma unroll
    for (int qc = 0; qc < 4; qc++) {
        float m = fmaxf(fmaxf(s[qc][0], s[qc][1]), fmaxf(s[qc][2], s[qc][3]));
        float e0 = expf(s[qc][0] - m), e1 = expf(s[qc][1] - m);
        float e2 = expf(s[qc][2] - m), e3 = expf(s[qc][3] - m);
        float inv = 1.0f / (e0 + e1 + e2 + e3);
        float o = (e0 * v[0] + e1 * v[1] + e2 * v[2] + e3 * v[3]) * inv;
        g_att[((long)qc * Bsz + b) * 128 + nh * 32 + lane] = o;
    }
}

// ---------------- LayerNorm over H=128 (in place on g_msg) ------------------
__global__ void ln_kernel(const float* __restrict__ gg, const float* __restrict__ bb)
{
    int row  = blockIdx.x * 4 + (threadIdx.x >> 5);
    int lane = threadIdx.x & 31;
    float* p = g_msg + (long)row * 128;

    float4 x = *(const float4*)(p + lane * 4);
    float s = x.x + x.y + x.z + x.w;
    #pragma unroll
    for (int off = 16; off > 0; off >>= 1) s += __shfl_xor_sync(0xFFFFFFFFu, s, off);
    float mean = s * (1.0f / 128.0f);

    float dx = x.x - mean, dy = x.y - mean, dz = x.z - mean, dw = x.w - mean;
    float sq = dx * dx + dy * dy + dz * dz + dw * dw;
    #pragma unroll
    for (int off = 16; off > 0; off >>= 1) sq += __shfl_xor_sync(0xFFFFFFFFu, sq, off);
    float rstd = rsqrtf(sq * (1.0f / 128.0f) + 1e-5f);

    float4 gv = *(const float4*)(gg + lane * 4);
    float4 bv = *(const float4*)(bb + lane * 4);
    float4 o;
    o.x = dx * rstd * gv.x + bv.x;
    o.y = dy * rstd * gv.y + bv.y;
    o.z = dz * rstd * gv.z + bv.z;
    o.w = dw * rstd * gv.w + bv.w;
    *(float4*)(p + lane * 4) = o;
}

// ---------------- gate + blend, writes final h_n for this layer -------------
__global__ void gate_kernel(const float* __restrict__ gw, const float* __restrict__ gbp,
                            float* __restrict__ hout)
{
    int row  = blockIdx.x * 4 + (threadIdx.x >> 5);
    int lane = threadIdx.x & 31;
    const float* hn = g_hn  + (long)row * 128;
    const float* ms = g_msg + (long)row * 128;

    float4 hv = *(const float4*)(hn + lane * 4);
    float4 mv = *(const float4*)(ms + lane * 4);
    float4 w1 = *(const float4*)(gw + lane * 4);
    float4 w2 = *(const float4*)(gw + 128 + lane * 4);

    float p = hv.x * w1.x + hv.y * w1.y + hv.z * w1.z + hv.w * w1.w
            + mv.x * w2.x + mv.y * w2.y + mv.z * w2.z + mv.w * w2.w;
    #pragma unroll
    for (int off = 16; off > 0; off >>= 1) p += __shfl_xor_sync(0xFFFFFFFFu, p, off);
    float gt = sigf(p + gbp[0]);

    float4 o;
    o.x = (1.0f - gt) * hv.x + gt * mv.x;
    o.y = (1.0f - gt) * hv.y + gt * mv.y;
    o.z = (1.0f - gt) * hv.z + gt * mv.z;
    o.w = (1.0f - gt) * hv.w + gt * mv.w;
    *(float4*)(hout + (long)row * 128 + lane * 4) = o;
}

// ---------------- host orchestration ----------------------------------------
extern "C" void kernel_launch(void* const* d_in, const int* in_sizes, int n_in,
                              void* d_out, int out_size)
{
    const int*   tokens     = (const int*)  d_in[0];
    const float* h_in       = (const float*)d_in[1];
    const float* emb        = (const float*)d_in[2];
    const float* wih0_c0    = (const float*)d_in[3];
    /* d_in[4] = wih0_rest, unused by the reference math */
    const float* bih0       = (const float*)d_in[5];
    const float* whh0       = (const float*)d_in[6];
    const float* bhh0       = (const float*)d_in[7];
    const float* wih        = (const float*)d_in[8];
    const float* whh        = (const float*)d_in[9];
    const float* bih        = (const float*)d_in[10];
    const float* bhh        = (const float*)d_in[11];
    const float* attn_in_w  = (const float*)d_in[12];
    const float* attn_in_b  = (const float*)d_in[13];
    const float* attn_out_w = (const float*)d_in[14];
    const float* attn_out_b = (const float*)d_in[15];
    const float* ln_g       = (const float*)d_in[16];
    const float* ln_b       = (const float*)d_in[17];
    const float* gate_w     = (const float*)d_in[18];
    const float* gate_b     = (const float*)d_in[19];
    const float* head_w     = (const float*)d_in[20];
    const float* head_b     = (const float*)d_in[21];

    float* yOut = (float*)d_out;                       // (B, O)
    float* hOut = yOut + (size_t)Bsz * Oo;             // (L, C, B, H)

    float *px0, *pgi, *pgh, *pqkv, *phn, *patt, *pmsg;
    cudaGetSymbolAddress((void**)&px0,  g_x0);
    cudaGetSymbolAddress((void**)&pgi,  g_gi);
    cudaGetSymbolAddress((void**)&pgh,  g_gh);
    cudaGetSymbolAddress((void**)&pqkv, g_qkv);
    cudaGetSymbolAddress((void**)&phn,  g_hn);
    cudaGetSymbolAddress((void**)&patt, g_att);
    cudaGetSymbolAddress((void**)&pmsg, g_msg);

    const long CBH  = (long)Cc * Bsz * Hd;
    const long CB3H = (long)Cc * Bsz * G3H;
    (void)CB3H; (void)in_sizes; (void)n_in; (void)out_size;

    dim3 gB(Bsz / 128, G3H / 64, Cc);     // 3H-output GEMMs, all cells
    dim3 gO(Bsz / 128, Hd  / 64, Cc);     // H-output GEMM (out proj)

    for (int l = 0; l < Ll; l++) {
        const float* hl = h_in + (size_t)l * CBH;

        // ---- gi ----
        if (l == 0) {
            gather_x0<<<(Bsz * 32) / 256, 256>>>(tokens, emb);
            dim3 g1(Bsz / 128, G3H / 64, 1);
            gemm_bias<<<g1, 256>>>(px0, wih0_c0, bih0, pgi, G3H, 0, 0, 0, 0);
            fill_gi0<<<(3 * Bsz * 96) / 256, 256>>>(bih0);
        } else {
            gemm_bias<<<gB, 256>>>(hOut + (size_t)(l - 1) * CBH,
                                   wih + (size_t)(l - 1) * Cc * G3H * Hd,
                                   bih + (size_t)(l - 1) * Cc * G3H,
                                   pgi, G3H,
                                   (long)Bsz * Hd, (long)G3H * Hd, G3H, (long)Bsz * G3H);
        }

        // ---- gh ----
        const float* whh_l = (l == 0) ? whh0 : whh + (size_t)(l - 1) * Cc * G3H * Hd;
        const float* bhh_l = (l == 0) ? bhh0 : bhh + (size_t)(l - 1) * Cc * G3H;
        gemm_bias<<<gB, 256>>>(hl, whh_l, bhh_l, pgh, G3H,
                               (long)Bsz * Hd, (long)G3H * Hd, G3H, (long)Bsz * G3H);

        // ---- GRU ----
        gru_kernel<<<((long)Cc * Bsz * 32) / 256, 256>>>(hl);

        // ---- QKV (weights shared across cells: strides 0) ----
        gemm_bias<<<gB, 256>>>(phn,
                               attn_in_w + (size_t)l * G3H * Hd,
                               attn_in_b + (size_t)l * G3H,
                               pqkv, G3H,
                               (long)Bsz * Hd, 0, 0, (long)Bsz * G3H);

        // ---- attention over 4 cells ----
        attn_kernel<<<(Bsz * NHh) / 4, 128>>>();

        // ---- out projection ----
        gemm_bias<<<gO, 256>>>(patt,
                               attn_out_w + (size_t)l * Hd * Hd,
                               attn_out_b + (size_t)l * Hd,
                               pmsg, Hd,
                               (long)Bsz * Hd, 0, 0, (long)Bsz * Hd);

        // ---- LayerNorm (in place on g_msg) ----
        ln_kernel<<<(Cc * Bsz) / 4, 128>>>(ln_g + (size_t)l * Hd, ln_b + (size_t)l * Hd);

        // ---- gate + blend -> h_n[l] ----
        gate_kernel<<<(Cc * Bsz) / 4, 128>>>(gate_w + (size_t)l * 2 * Hd,
                                             gate_b + l,
                                             hOut + (size_t)l * CBH);
    }

    // ---- head: y = h_n[L-1, 0] @ head_w.T + head_b ----
    dim3 gH(Bsz / 128, Oo / 64, 1);
    gemm_bias<<<gH, 256>>>(hOut + (size_t)(Ll - 1) * CBH, head_w, head_b,
                           yOut, Oo, 0, 0, 0, 0);
}

// round 3
// speedup vs baseline: 1.5439x; 1.5439x over previous
#include <cuda_runtime.h>
#include <cuda_bf16.h>
#include <math.h>
#include <stdint.h>

#define Bsz 16384
#define Hd  128
#define Cc  4
#define Ll  6
#define NHh 4
#define HDd 32
#define Oo  1024
#define G3H 384

// ---------------- scratch (static device globals; no allocations) ----------
__device__ float g_x0 [(size_t)Bsz * Hd];
__device__ float g_gi [(size_t)Cc * Bsz * G3H];
__device__ float g_gh [(size_t)Cc * Bsz * G3H];
__device__ float g_qkv[(size_t)Cc * Bsz * G3H];
__device__ float g_hn [(size_t)Cc * Bsz * Hd];
__device__ float g_att[(size_t)Cc * Bsz * Hd];
__device__ float g_msg[(size_t)Cc * Bsz * Hd];

__device__ __forceinline__ float sigf(float x) { return 1.0f / (1.0f + expf(-x)); }

// ======================= HMMA (mma.sync) GEMM =======================
// Y[c,b,g] = sum_k X[c,b,k] * W[c,g,k] + bias[c,g],  K = 128 fixed.
// CTA tile: 128(b) x 128(g). 8 warps, warp tile 64(m) x 32(n).
// fp32 operands split into bf16 hi+lo; D = Ah*Bh + Ah*Bl + Al*Bh (fp32 accum).

#define KPAD   136                 // 128 + 8 bf16 padding (272B row stride)
#define TILE_B ((size_t)128 * KPAD * 2)   // 34816 bytes per bf16 tile
#define SM_AH  0
#define SM_AL  (SM_AH + TILE_B)
#define SM_BH  (SM_AL + TILE_B)
#define SM_BL  (SM_BH + TILE_B)
#define SM_TOT (SM_BL + TILE_B)    // 139264 bytes

__device__ __forceinline__ uint32_t pack_bf16(__nv_bfloat16 a, __nv_bfloat16 b) {
    __nv_bfloat162 t = __nv_bfloat162(a, b);
    return *reinterpret_cast<uint32_t*>(&t);
}

__device__ __forceinline__ void mma16816(float* c, uint32_t a0, uint32_t a1,
                                         uint32_t a2, uint32_t a3,
                                         uint32_t b0, uint32_t b1) {
    asm volatile(
        "mma.sync.aligned.m16n8k16.row.col.f32.bf16.bf16.f32 "
        "{%0,%1,%2,%3}, {%4,%5,%6,%7}, {%8,%9}, {%0,%1,%2,%3};\n"
        : "+f"(c[0]), "+f"(c[1]), "+f"(c[2]), "+f"(c[3])
        : "r"(a0), "r"(a1), "r"(a2), "r"(a3), "r"(b0), "r"(b1));
}

// Load 128x128 f32 tile (row stride 128) -> bf16 hi/lo SMEM tiles (k-padded).
__device__ __forceinline__ void fill_split(const float* __restrict__ g,
                                           char* smem, int off_hi, int off_lo, int tid) {
    #pragma unroll 4
    for (int idx = tid; idx < 4096; idx += 256) {
        int row = idx >> 5;
        int c4  = idx & 31;
        float4 v = *reinterpret_cast<const float4*>(g + (long)row * 128 + c4 * 4);

        __nv_bfloat16 h0 = __float2bfloat16(v.x);
        __nv_bfloat16 h1 = __float2bfloat16(v.y);
        __nv_bfloat16 h2 = __float2bfloat16(v.z);
        __nv_bfloat16 h3 = __float2bfloat16(v.w);
        __nv_bfloat16 l0 = __float2bfloat16(v.x - __bfloat162float(h0));
        __nv_bfloat16 l1 = __float2bfloat16(v.y - __bfloat162float(h1));
        __nv_bfloat16 l2 = __float2bfloat16(v.z - __bfloat162float(h2));
        __nv_bfloat16 l3 = __float2bfloat16(v.w - __bfloat162float(h3));

        int boff = row * (KPAD * 2) + c4 * 8;   // bytes
        *reinterpret_cast<uint2*>(smem + off_hi + boff) =
            make_uint2(pack_bf16(h0, h1), pack_bf16(h2, h3));
        *reinterpret_cast<uint2*>(smem + off_lo + boff) =
            make_uint2(pack_bf16(l0, l1), pack_bf16(l2, l3));
    }
}

__device__ __forceinline__ uint32_t lds32(const char* smem, int off, int row, int k) {
    return *reinterpret_cast<const uint32_t*>(smem + off + row * (KPAD * 2) + k * 2);
}

__global__ __launch_bounds__(256, 1) void gemm_tc(
    const float* __restrict__ X, const float* __restrict__ W,
    const float* __restrict__ bias, float* __restrict__ Y,
    int G, long xStride, long wStride, long bStride, long yStride)
{
    extern __shared__ char smem[];

    int c = blockIdx.z;
    X    += (long)c * xStride;
    W    += (long)c * wStride;
    bias += (long)c * bStride;
    Y    += (long)c * yStride;

    int b0  = blockIdx.x * 128;
    int g0  = blockIdx.y * 128;
    int tid = threadIdx.x;
    int wid = tid >> 5;
    int lane = tid & 31;

    fill_split(X + (long)b0 * 128, smem, SM_AH, SM_AL, tid);
    fill_split(W + (long)g0 * 128, smem, SM_BH, SM_BL, tid);
    __syncthreads();

    int wm = (wid & 1) * 64;    // warp m offset within CTA tile
    int wn = (wid >> 1) * 32;   // warp n offset

    int arow = wm + (lane >> 2);        // base A row for this lane
    int brow = wn + (lane >> 2);        // base B row (n index)
    int kl   = (lane & 3) * 2;          // base k within k16 step

    float acc[4][4][4];
    #pragma unroll
    for (int i = 0; i < 4; i++)
        #pragma unroll
        for (int j = 0; j < 4; j++)
            #pragma unroll
            for (int r = 0; r < 4; r++) acc[i][j][r] = 0.0f;

    #pragma unroll 2
    for (int kk = 0; kk < 8; kk++) {
        int k0 = kk * 16 + kl;

        uint32_t ah[4][4], al[4][4];
        #pragma unroll
        for (int i = 0; i < 4; i++) {
            int r0 = arow + i * 16;
            ah[i][0] = lds32(smem, SM_AH, r0,     k0);
            ah[i][1] = lds32(smem, SM_AH, r0 + 8, k0);
            ah[i][2] = lds32(smem, SM_AH, r0,     k0 + 8);
            ah[i][3] = lds32(smem, SM_AH, r0 + 8, k0 + 8);
            al[i][0] = lds32(smem, SM_AL, r0,     k0);
            al[i][1] = lds32(smem, SM_AL, r0 + 8, k0);
            al[i][2] = lds32(smem, SM_AL, r0,     k0 + 8);
            al[i][3] = lds32(smem, SM_AL, r0 + 8, k0 + 8);
        }
        uint32_t bh[4][2], bl[4][2];
        #pragma unroll
        for (int j = 0; j < 4; j++) {
            int n0 = brow + j * 8;
            bh[j][0] = lds32(smem, SM_BH, n0, k0);
            bh[j][1] = lds32(smem, SM_BH, n0, k0 + 8);
            bl[j][0] = lds32(smem, SM_BL, n0, k0);
            bl[j][1] = lds32(smem, SM_BL, n0, k0 + 8);
        }

        #pragma unroll
        for (int i = 0; i < 4; i++)
            #pragma unroll
            for (int j = 0; j < 4; j++) {
                mma16816(acc[i][j], ah[i][0], ah[i][1], ah[i][2], ah[i][3], bh[j][0], bh[j][1]);
                mma16816(acc[i][j], ah[i][0], ah[i][1], ah[i][2], ah[i][3], bl[j][0], bl[j][1]);
                mma16816(acc[i][j], al[i][0], al[i][1], al[i][2], al[i][3], bh[j][0], bh[j][1]);
            }
    }

    // epilogue: c0,c1 -> (row, col..col+1); c2,c3 -> (row+8, col..col+1)
    int colb = g0 + wn + (lane & 3) * 2;
    #pragma unroll
    for (int i = 0; i < 4; i++) {
        int row = b0 + wm + i * 16 + (lane >> 2);
        #pragma unroll
        for (int j = 0; j < 4; j++) {
            int col = colb + j * 8;
            float bx = bias[col], by = bias[col + 1];
            float2 o0 = make_float2(acc[i][j][0] + bx, acc[i][j][1] + by);
            float2 o1 = make_float2(acc[i][j][2] + bx, acc[i][j][3] + by);
            *reinterpret_cast<float2*>(Y + (long)row * G + col)       = o0;
            *reinterpret_cast<float2*>(Y + (long)(row + 8) * G + col) = o1;
        }
    }
}

// ---------------- embedding gather: x0[b,:] = emb[tokens[b],:] --------------
__global__ void gather_x0(const int* __restrict__ tok, const float* __restrict__ emb)
{
    long t = (long)blockIdx.x * 256 + threadIdx.x;   // B*32 threads
    int b  = (int)(t >> 5);
    int e4 = (int)(t & 31) << 2;
    float4 v = *(const float4*)(emb + (long)tok[b] * 128 + e4);
    *(float4*)(g_x0 + (long)b * 128 + e4) = v;
}

// ---------------- l=0 cells 1..3: gi = bias broadcast -----------------------
__global__ void fill_gi0(const float* __restrict__ bih0)
{
    long t = (long)blockIdx.x * 256 + threadIdx.x;   // 3*B*96 float4 units
    int  g4  = (int)(t % 96) * 4;
    long rem = t / 96;
    int  b   = (int)(rem % Bsz);
    int  c   = 1 + (int)(rem / Bsz);
    float4 v = *(const float4*)(bih0 + (long)c * G3H + g4);
    *(float4*)(g_gi + ((long)c * Bsz + b) * G3H + g4) = v;
}

// ---------------- GRU elementwise -------------------------------------------
__global__ void gru_kernel(const float* __restrict__ hprev)
{
    long t   = (long)blockIdx.x * 256 + threadIdx.x;   // C*B*32
    long row = t >> 5;
    int  h4  = (int)(t & 31) << 2;
    const float* gi = g_gi + row * G3H;
    const float* gh = g_gh + row * G3H;

    float4 ir  = *(const float4*)(gi + h4);
    float4 iz  = *(const float4*)(gi + 128 + h4);
    float4 inn = *(const float4*)(gi + 256 + h4);
    float4 hr  = *(const float4*)(gh + h4);
    float4 hz  = *(const float4*)(gh + 128 + h4);
    float4 hnn = *(const float4*)(gh + 256 + h4);
    float4 hp  = *(const float4*)(hprev + row * 128 + h4);

    float4 out;
    {
        float r = sigf(ir.x + hr.x), z = sigf(iz.x + hz.x);
        float n = tanhf(inn.x + r * hnn.x);
        out.x = (1.0f - z) * n + z * hp.x;
    }
    {
        float r = sigf(ir.y + hr.y), z = sigf(iz.y + hz.y);
        float n = tanhf(inn.y + r * hnn.y);
        out.y = (1.0f - z) * n + z * hp.y;
    }
    {
        float r = sigf(ir.z + hr.z), z = sigf(iz.z + hz.z);
        float n = tanhf(inn.z + r * hnn.z);
        out.z = (1.0f - z) * n + z * hp.z;
    }
    {
        float r = sigf(ir.w + hr.w), z = sigf(iz.w + hz.w);
        float n = tanhf(inn.w + r * hnn.w);
        out.w = (1.0f - z) * n + z * hp.w;
    }
    *(float4*)(g_hn + row * 128 + h4) = out;
}

// ---------------- tiny attention over C=4 positions --------------------------
__global__ void attn_kernel()
{
    int gw   = blockIdx.x * 4 + (threadIdx.x >> 5);   // (b, nh) index
    int lane = threadIdx.x & 31;                      // = head dim
    int b  = gw >> 2;
    int nh = gw & 3;

    float q[4], k[4], v[4];
    #pragma unroll
    for (int c = 0; c < 4; c++) {
        const float* p = g_qkv + ((long)c * Bsz + b) * G3H + nh * 32 + lane;
        q[c] = p[0];
        k[c] = p[128];
        v[c] = p[256];
    }

    float s[4][4];
    #pragma unroll
    for (int qc = 0; qc < 4; qc++) {
        #pragma unroll
        for (int kc = 0; kc < 4; kc++) {
            float p = q[qc] * k[kc];
            #pragma unroll
            for (int off = 16; off > 0; off >>= 1)
                p += __shfl_xor_sync(0xFFFFFFFFu, p, off);
            s[qc][kc] = p * 0.17677669529663687f;   // 1/sqrt(32)
        }
    }

    #pragma unroll
    for (int qc = 0; qc < 4; qc++) {
        float m = fmaxf(fmaxf(s[qc][0], s[qc][1]), fmaxf(s[qc][2], s[qc][3]));
        float e0 = expf(s[qc][0] - m), e1 = expf(s[qc][1] - m);
        float e2 = expf(s[qc][2] - m), e3 = expf(s[qc][3] - m);
        float inv = 1.0f / (e0 + e1 + e2 + e3);
        float o = (e0 * v[0] + e1 * v[1] + e2 * v[2] + e3 * v[3]) * inv;
        g_att[((long)qc * Bsz + b) * 128 + nh * 32 + lane] = o;
    }
}

// ---------------- LayerNorm over H=128 (in place on g_msg) ------------------
__global__ void ln_kernel(const float* __restrict__ gg, const float* __restrict__ bb)
{
    int row  = blockIdx.x * 4 + (threadIdx.x >> 5);
    int lane = threadIdx.x & 31;
    float* p = g_msg + (long)row * 128;

    float4 x = *(const float4*)(p + lane * 4);
    float s = x.x + x.y + x.z + x.w;
    #pragma unroll
    for (int off = 16; off > 0; off >>= 1) s += __shfl_xor_sync(0xFFFFFFFFu, s, off);
    float mean = s * (1.0f / 128.0f);

    float dx = x.x - mean, dy = x.y - mean, dz = x.z - mean, dw = x.w - mean;
    float sq = dx * dx + dy * dy + dz * dz + dw * dw;
    #pragma unroll
    for (int off = 16; off > 0; off >>= 1) sq += __shfl_xor_sync(0xFFFFFFFFu, sq, off);
    float rstd = rsqrtf(sq * (1.0f / 128.0f) + 1e-5f);

    float4 gv = *(const float4*)(gg + lane * 4);
    float4 bv = *(const float4*)(bb + lane * 4);
    float4 o;
    o.x = dx * rstd * gv.x + bv.x;
    o.y = dy * rstd * gv.y + bv.y;
    o.z = dz * rstd * gv.z + bv.z;
    o.w = dw * rstd * gv.w + bv.w;
    *(float4*)(p + lane * 4) = o;
}

// ---------------- gate + blend, writes final h_n for this layer -------------
__global__ void gate_kernel(const float* __restrict__ gw, const float* __restrict__ gbp,
                            float* __restrict__ hout)
{
    int row  = blockIdx.x * 4 + (threadIdx.x >> 5);
    int lane = threadIdx.x & 31;
    const float* hn = g_hn  + (long)row * 128;
    const float* ms = g_msg + (long)row * 128;

    float4 hv = *(const float4*)(hn + lane * 4);
    float4 mv = *(const float4*)(ms + lane * 4);
    float4 w1 = *(const float4*)(gw + lane * 4);
    float4 w2 = *(const float4*)(gw + 128 + lane * 4);

    float p = hv.x * w1.x + hv.y * w1.y + hv.z * w1.z + hv.w * w1.w
            + mv.x * w2.x + mv.y * w2.y + mv.z * w2.z + mv.w * w2.w;
    #pragma unroll
    for (int off = 16; off > 0; off >>= 1) p += __shfl_xor_sync(0xFFFFFFFFu, p, off);
    float gt = sigf(p + gbp[0]);

    float4 o;
    o.x = (1.0f - gt) * hv.x + gt * mv.x;
    o.y = (1.0f - gt) * hv.y + gt * mv.y;
    o.z = (1.0f - gt) * hv.z + gt * mv.z;
    o.w = (1.0f - gt) * hv.w + gt * mv.w;
    *(float4*)(hout + (long)row * 128 + lane * 4) = o;
}

// ---------------- host orchestration ----------------------------------------
extern "C" void kernel_launch(void* const* d_in, const int* in_sizes, int n_in,
                              void* d_out, int out_size)
{
    const int*   tokens     = (const int*)  d_in[0];
    const float* h_in       = (const float*)d_in[1];
    const float* emb        = (const float*)d_in[2];
    const float* wih0_c0    = (const float*)d_in[3];
    /* d_in[4] = wih0_rest, unused by the reference math */
    const float* bih0       = (const float*)d_in[5];
    const float* whh0       = (const float*)d_in[6];
    const float* bhh0       = (const float*)d_in[7];
    const float* wih        = (const float*)d_in[8];
    const float* whh        = (const float*)d_in[9];
    const float* bih        = (const float*)d_in[10];
    const float* bhh        = (const float*)d_in[11];
    const float* attn_in_w  = (const float*)d_in[12];
    const float* attn_in_b  = (const float*)d_in[13];
    const float* attn_out_w = (const float*)d_in[14];
    const float* attn_out_b = (const float*)d_in[15];
    const float* ln_g       = (const float*)d_in[16];
    const float* ln_b       = (const float*)d_in[17];
    const float* gate_w     = (const float*)d_in[18];
    const float* gate_b     = (const float*)d_in[19];
    const float* head_w     = (const float*)d_in[20];
    const float* head_b     = (const float*)d_in[21];

    float* yOut = (float*)d_out;                       // (B, O)
    float* hOut = yOut + (size_t)Bsz * Oo;             // (L, C, B, H)

    float *px0, *pgi, *pgh, *pqkv, *phn, *patt, *pmsg;
    cudaGetSymbolAddress((void**)&px0,  g_x0);
    cudaGetSymbolAddress((void**)&pgi,  g_gi);
    cudaGetSymbolAddress((void**)&pgh,  g_gh);
    cudaGetSymbolAddress((void**)&pqkv, g_qkv);
    cudaGetSymbolAddress((void**)&phn,  g_hn);
    cudaGetSymbolAddress((void**)&patt, g_att);
    cudaGetSymbolAddress((void**)&pmsg, g_msg);

    cudaFuncSetAttribute(gemm_tc, cudaFuncAttributeMaxDynamicSharedMemorySize, SM_TOT);

    const long CBH = (long)Cc * Bsz * Hd;
    (void)in_sizes; (void)n_in; (void)out_size;

    dim3 gB(Bsz / 128, G3H / 128, Cc);     // 3H-output GEMMs, all cells
    dim3 gO(Bsz / 128, Hd  / 128, Cc);     // H-output GEMM (out proj)

    for (int l = 0; l < Ll; l++) {
        const float* hl = h_in + (size_t)l * CBH;

        // ---- gi ----
        if (l == 0) {
            gather_x0<<<(Bsz * 32) / 256, 256>>>(tokens, emb);
            dim3 g1(Bsz / 128, G3H / 128, 1);
            gemm_tc<<<g1, 256, SM_TOT>>>(px0, wih0_c0, bih0, pgi, G3H, 0, 0, 0, 0);
            fill_gi0<<<(3 * Bsz * 96) / 256, 256>>>(bih0);
        } else {
            gemm_tc<<<gB, 256, SM_TOT>>>(hOut + (size_t)(l - 1) * CBH,
                                         wih + (size_t)(l - 1) * Cc * G3H * Hd,
                                         bih + (size_t)(l - 1) * Cc * G3H,
                                         pgi, G3H,
                                         (long)Bsz * Hd, (long)G3H * Hd, G3H, (long)Bsz * G3H);
        }

        // ---- gh ----
        const float* whh_l = (l == 0) ? whh0 : whh + (size_t)(l - 1) * Cc * G3H * Hd;
        const float* bhh_l = (l == 0) ? bhh0 : bhh + (size_t)(l - 1) * Cc * G3H;
        gemm_tc<<<gB, 256, SM_TOT>>>(hl, whh_l, bhh_l, pgh, G3H,
                                     (long)Bsz * Hd, (long)G3H * Hd, G3H, (long)Bsz * G3H);

        // ---- GRU ----
        gru_kernel<<<((long)Cc * Bsz * 32) / 256, 256>>>(hl);

        // ---- QKV (weights shared across cells: strides 0) ----
        gemm_tc<<<gB, 256, SM_TOT>>>(phn,
                                     attn_in_w + (size_t)l * G3H * Hd,
                                     attn_in_b + (size_t)l * G3H,
                                     pqkv, G3H,
                                     (long)Bsz * Hd, 0, 0, (long)Bsz * G3H);

        // ---- attention over 4 cells ----
        attn_kernel<<<(Bsz * NHh) / 4, 128>>>();

        // ---- out projection ----
        gemm_tc<<<gO, 256, SM_TOT>>>(patt,
                                     attn_out_w + (size_t)l * Hd * Hd,
                                     attn_out_b + (size_t)l * Hd,
                                     pmsg, Hd,
                                     (long)Bsz * Hd, 0, 0, (long)Bsz * Hd);

        // ---- LayerNorm (in place on g_msg) ----
        ln_kernel<<<(Cc * Bsz) / 4, 128>>>(ln_g + (size_t)l * Hd, ln_b + (size_t)l * Hd);

        // ---- gate + blend -> h_n[l] ----
        gate_kernel<<<(Cc * Bsz) / 4, 128>>>(gate_w + (size_t)l * 2 * Hd,
                                             gate_b + l,
                                             hOut + (size_t)l * CBH);
    }

    // ---- head: y = h_n[L-1, 0] @ head_w.T + head_b ----
    dim3 gH(Bsz / 128, Oo / 128, 1);
    gemm_tc<<<gH, 256, SM_TOT>>>(hOut + (size_t)(Ll - 1) * CBH, head_w, head_b,
                                 yOut, Oo, 0, 0, 0, 0);
}

// round 4
// speedup vs baseline: 1.5461x; 1.0014x over previous
#include <cuda_runtime.h>
#include <cuda_bf16.h>
#include <math.h>
#include <stdint.h>

#define Bsz 16384
#define Hd  128
#define Cc  4
#define Ll  6
#define NHh 4
#define HDd 32
#define Oo  1024
#define G3H 384

// ---------------- scratch (static device globals; no allocations) ----------
__device__ float g_x0 [(size_t)Bsz * Hd];
__device__ float g_gi [(size_t)Cc * Bsz * G3H];
__device__ float g_gh [(size_t)Cc * Bsz * G3H];
__device__ float g_qkv[(size_t)Cc * Bsz * G3H];
__device__ float g_hn [(size_t)Cc * Bsz * Hd];
__device__ float g_att[(size_t)Cc * Bsz * Hd];
__device__ float g_msg[(size_t)Cc * Bsz * Hd];

__device__ __forceinline__ float sigf(float x) { return 1.0f / (1.0f + expf(-x)); }

// ======================= HMMA (mma.sync) GEMM =======================
// Y[c,b,g] = sum_k X[c,b,k] * W[c,g,k] + bias[c,g],  K = 128 fixed.
// CTA tile: 128(b) x 128(g). 8 warps, warp tile 64(m) x 32(n).
// fp32 operands split into bf16 hi+lo; D = Ah*Bh + Ah*Bl + Al*Bh (fp32 accum).
// Mainloop: ldmatrix.x4 fragment loads, full unroll, register double-buffer.

#define KPAD    136                 // 128 + 8 bf16 padding (272B row stride)
#define ROWB    (KPAD * 2)          // 272 bytes per row
#define TILE_B  ((size_t)128 * ROWB)
#define SM_AH   0
#define SM_AL   (SM_AH + TILE_B)
#define SM_BH   (SM_AL + TILE_B)
#define SM_BL   (SM_BH + TILE_B)
#define SM_TOT  (SM_BL + TILE_B)    // 139264 bytes

__device__ __forceinline__ uint32_t smem_u32(const void* p) {
    uint32_t a;
    asm("{ .reg .u64 t; cvta.to.shared.u64 t, %1; cvt.u32.u64 %0, t; }" : "=r"(a) : "l"(p));
    return a;
}

__device__ __forceinline__ uint32_t pack_bf16(__nv_bfloat16 a, __nv_bfloat16 b) {
    __nv_bfloat162 t = __nv_bfloat162(a, b);
    return *reinterpret_cast<uint32_t*>(&t);
}

__device__ __forceinline__ void mma16816(float* c, const uint32_t* a, const uint32_t* b) {
    asm volatile(
        "mma.sync.aligned.m16n8k16.row.col.f32.bf16.bf16.f32 "
        "{%0,%1,%2,%3}, {%4,%5,%6,%7}, {%8,%9}, {%0,%1,%2,%3};\n"
        : "+f"(c[0]), "+f"(c[1]), "+f"(c[2]), "+f"(c[3])
        : "r"(a[0]), "r"(a[1]), "r"(a[2]), "r"(a[3]), "r"(b[0]), "r"(b[1]));
}

#define LDSM_X4(r0, r1, r2, r3, addr) \
    asm volatile("ldmatrix.sync.aligned.m8n8.x4.shared.b16 {%0,%1,%2,%3}, [%4];" \
                 : "=r"(r0), "=r"(r1), "=r"(r2), "=r"(r3) : "r"(addr))

struct Frags {
    uint32_t ah[4][4];
    uint32_t al[4][4];
    uint32_t bh[4][2];
    uint32_t bl[4][2];
};

// Load all fragments for one k16-step. aH/aL: A hi/lo lane addresses,
// bH/bL: B hi/lo lane addresses (already include the k-step offset).
__device__ __forceinline__ void ld_frags(Frags& f, uint32_t aH, uint32_t aL,
                                         uint32_t bH, uint32_t bL) {
    #pragma unroll
    for (int i = 0; i < 4; i++)
        LDSM_X4(f.ah[i][0], f.ah[i][1], f.ah[i][2], f.ah[i][3], aH + i * (16 * ROWB));
    #pragma unroll
    for (int i = 0; i < 4; i++)
        LDSM_X4(f.al[i][0], f.al[i][1], f.al[i][2], f.al[i][3], aL + i * (16 * ROWB));
    LDSM_X4(f.bh[0][0], f.bh[0][1], f.bh[1][0], f.bh[1][1], bH);
    LDSM_X4(f.bh[2][0], f.bh[2][1], f.bh[3][0], f.bh[3][1], bH + 16 * ROWB);
    LDSM_X4(f.bl[0][0], f.bl[0][1], f.bl[1][0], f.bl[1][1], bL);
    LDSM_X4(f.bl[2][0], f.bl[2][1], f.bl[3][0], f.bl[3][1], bL + 16 * ROWB);
}

// Load 128x128 f32 tile (row stride 128) -> bf16 hi/lo SMEM tiles (k-padded).
__device__ __forceinline__ void fill_split(const float* __restrict__ g,
                                           char* smem, int off_hi, int off_lo, int tid) {
    #pragma unroll 4
    for (int idx = tid; idx < 4096; idx += 256) {
        int row = idx >> 5;
        int c4  = idx & 31;
        float4 v = *reinterpret_cast<const float4*>(g + (long)row * 128 + c4 * 4);

        __nv_bfloat16 h0 = __float2bfloat16(v.x);
        __nv_bfloat16 h1 = __float2bfloat16(v.y);
        __nv_bfloat16 h2 = __float2bfloat16(v.z);
        __nv_bfloat16 h3 = __float2bfloat16(v.w);
        __nv_bfloat16 l0 = __float2bfloat16(v.x - __bfloat162float(h0));
        __nv_bfloat16 l1 = __float2bfloat16(v.y - __bfloat162float(h1));
        __nv_bfloat16 l2 = __float2bfloat16(v.z - __bfloat162float(h2));
        __nv_bfloat16 l3 = __float2bfloat16(v.w - __bfloat162float(h3));

        int boff = row * ROWB + c4 * 8;   // bytes
        *reinterpret_cast<uint2*>(smem + off_hi + boff) =
            make_uint2(pack_bf16(h0, h1), pack_bf16(h2, h3));
        *reinterpret_cast<uint2*>(smem + off_lo + boff) =
            make_uint2(pack_bf16(l0, l1), pack_bf16(l2, l3));
    }
}

__global__ __launch_bounds__(256, 1) void gemm_tc(
    const float* __restrict__ X, const float* __restrict__ W,
    const float* __restrict__ bias, float* __restrict__ Y,
    int G, long xStride, long wStride, long bStride, long yStride)
{
    extern __shared__ char smem[];

    int c = blockIdx.z;
    X    += (long)c * xStride;
    W    += (long)c * wStride;
    bias += (long)c * bStride;
    Y    += (long)c * yStride;

    int b0   = blockIdx.x * 128;
    int g0   = blockIdx.y * 128;
    int tid  = threadIdx.x;
    int wid  = tid >> 5;
    int lane = tid & 31;

    fill_split(X + (long)b0 * 128, smem, SM_AH, SM_AL, tid);
    fill_split(W + (long)g0 * 128, smem, SM_BH, SM_BL, tid);
    __syncthreads();

    int wm = (wid & 1) * 64;    // warp m offset within CTA tile
    int wn = (wid >> 1) * 32;   // warp n offset

    // ldmatrix lane addressing:
    // A m16k16 block: T0=(r0..7,klo) T1=(r8..15,klo) T2=(r0..7,khi) T3=(r8..15,khi)
    //   -> regs a0,a1,a2,a3 of mma. lanes 0-7->T0, 8-15->T1, 16-23->T2, 24-31->T3.
    // B n16k16 block: T0=(n0..7,klo) T1=(n0..7,khi) T2=(n8..15,klo) T3=(n8..15,khi)
    //   -> regs bh[j][0],bh[j][1],bh[j+1][0],bh[j+1][1].
    uint32_t sbase = smem_u32(smem);
    int a_lane = (wm + (lane & 7) + ((lane >> 3) & 1) * 8) * ROWB + (lane >> 4) * 16;
    int b_lane = (wn + (lane & 7) + ((lane >> 4) & 1) * 8) * ROWB + ((lane >> 3) & 1) * 16;

    uint32_t aH = sbase + SM_AH + a_lane;
    uint32_t aL = sbase + SM_AL + a_lane;
    uint32_t bH = sbase + SM_BH + b_lane;
    uint32_t bL = sbase + SM_BL + b_lane;

    float acc[4][4][4];
    #pragma unroll
    for (int i = 0; i < 4; i++)
        #pragma unroll
        for (int j = 0; j < 4; j++)
            #pragma unroll
            for (int r = 0; r < 4; r++) acc[i][j][r] = 0.0f;

    Frags fr[2];
    ld_frags(fr[0], aH, aL, bH, bL);

    #pragma unroll
    for (int kk = 0; kk < 8; kk++) {
        if (kk < 7) {
            int ko = (kk + 1) * 32;   // 16 bf16 = 32 bytes per k-step
            ld_frags(fr[(kk + 1) & 1], aH + ko, aL + ko, bH + ko, bL + ko);
        }
        Frags& f = fr[kk & 1];
        #pragma unroll
        for (int i = 0; i < 4; i++)
            #pragma unroll
            for (int j = 0; j < 4; j++) {
                mma16816(acc[i][j], f.ah[i], f.bh[j]);
                mma16816(acc[i][j], f.ah[i], f.bl[j]);
                mma16816(acc[i][j], f.al[i], f.bh[j]);
            }
    }

    // epilogue: c0,c1 -> (row, col..col+1); c2,c3 -> (row+8, col..col+1)
    int colb = g0 + wn + (lane & 3) * 2;
    #pragma unroll
    for (int i = 0; i < 4; i++) {
        int row = b0 + wm + i * 16 + (lane >> 2);
        #pragma unroll
        for (int j = 0; j < 4; j++) {
            int col = colb + j * 8;
            float bx = bias[col], by = bias[col + 1];
            float2 o0 = make_float2(acc[i][j][0] + bx, acc[i][j][1] + by);
            float2 o1 = make_float2(acc[i][j][2] + bx, acc[i][j][3] + by);
            *reinterpret_cast<float2*>(Y + (long)row * G + col)       = o0;
            *reinterpret_cast<float2*>(Y + (long)(row + 8) * G + col) = o1;
        }
    }
}

// ---------------- embedding gather: x0[b,:] = emb[tokens[b],:] --------------
__global__ void gather_x0(const int* __restrict__ tok, const float* __restrict__ emb)
{
    long t = (long)blockIdx.x * 256 + threadIdx.x;   // B*32 threads
    int b  = (int)(t >> 5);
    int e4 = (int)(t & 31) << 2;
    float4 v = *(const float4*)(emb + (long)tok[b] * 128 + e4);
    *(float4*)(g_x0 + (long)b * 128 + e4) = v;
}

// ---------------- l=0 cells 1..3: gi = bias broadcast -----------------------
__global__ void fill_gi0(const float* __restrict__ bih0)
{
    long t = (long)blockIdx.x * 256 + threadIdx.x;   // 3*B*96 float4 units
    int  g4  = (int)(t % 96) * 4;
    long rem = t / 96;
    int  b   = (int)(rem % Bsz);
    int  c   = 1 + (int)(rem / Bsz);
    float4 v = *(const float4*)(bih0 + (long)c * G3H + g4);
    *(float4*)(g_gi + ((long)c * Bsz + b) * G3H + g4) = v;
}

// ---------------- GRU elementwise -------------------------------------------
__global__ void gru_kernel(const float* __restrict__ hprev)
{
    long t   = (long)blockIdx.x * 256 + threadIdx.x;   // C*B*32
    long row = t >> 5;
    int  h4  = (int)(t & 31) << 2;
    const float* gi = g_gi + row * G3H;
    const float* gh = g_gh + row * G3H;

    float4 ir  = *(const float4*)(gi + h4);
    float4 iz  = *(const float4*)(gi + 128 + h4);
    float4 inn = *(const float4*)(gi + 256 + h4);
    float4 hr  = *(const float4*)(gh + h4);
    float4 hz  = *(const float4*)(gh + 128 + h4);
    float4 hnn = *(const float4*)(gh + 256 + h4);
    float4 hp  = *(const float4*)(hprev + row * 128 + h4);

    float4 out;
    {
        float r = sigf(ir.x + hr.x), z = sigf(iz.x + hz.x);
        float n = tanhf(inn.x + r * hnn.x);
        out.x = (1.0f - z) * n + z * hp.x;
    }
    {
        float r = sigf(ir.y + hr.y), z = sigf(iz.y + hz.y);
        float n = tanhf(inn.y + r * hnn.y);
        out.y = (1.0f - z) * n + z * hp.y;
    }
    {
        float r = sigf(ir.z + hr.z), z = sigf(iz.z + hz.z);
        float n = tanhf(inn.z + r * hnn.z);
        out.z = (1.0f - z) * n + z * hp.z;
    }
    {
        float r = sigf(ir.w + hr.w), z = sigf(iz.w + hz.w);
        float n = tanhf(inn.w + r * hnn.w);
        out.w = (1.0f - z) * n + z * hp.w;
    }
    *(float4*)(g_hn + row * 128 + h4) = out;
}

// ---------------- tiny attention over C=4 positions --------------------------
__global__ void attn_kernel()
{
    int gw   = blockIdx.x * 4 + (threadIdx.x >> 5);   // (b, nh) index
    int lane = threadIdx.x & 31;                      // = head dim
    int b  = gw >> 2;
    int nh = gw & 3;

    float q[4], k[4], v[4];
    #pragma unroll
    for (int c = 0; c < 4; c++) {
        const float* p = g_qkv + ((long)c * Bsz + b) * G3H + nh * 32 + lane;
        q[c] = p[0];
        k[c] = p[128];
        v[c] = p[256];
    }

    float s[4][4];
    #pragma unroll
    for (int qc = 0; qc < 4; qc++) {
        #pragma unroll
        for (int kc = 0; kc < 4; kc++) {
            float p = q[qc] * k[kc];
            #pragma unroll
            for (int off = 16; off > 0; off >>= 1)
                p += __shfl_xor_sync(0xFFFFFFFFu, p, off);
            s[qc][kc] = p * 0.17677669529663687f;   // 1/sqrt(32)
        }
    }

    #pragma unroll
    for (int qc = 0; qc < 4; qc++) {
        float m = fmaxf(fmaxf(s[qc][0], s[qc][1]), fmaxf(s[qc][2], s[qc][3]));
        float e0 = expf(s[qc][0] - m), e1 = expf(s[qc][1] - m);
        float e2 = expf(s[qc][2] - m), e3 = expf(s[qc][3] - m);
        float inv = 1.0f / (e0 + e1 + e2 + e3);
        float o = (e0 * v[0] + e1 * v[1] + e2 * v[2] + e3 * v[3]) * inv;
        g_att[((long)qc * Bsz + b) * 128 + nh * 32 + lane] = o;
    }
}

// ---------------- LayerNorm over H=128 (in place on g_msg) ------------------
__global__ void ln_kernel(const float* __restrict__ gg, const float* __restrict__ bb)
{
    int row  = blockIdx.x * 4 + (threadIdx.x >> 5);
    int lane = threadIdx.x & 31;
    float* p = g_msg + (long)row * 128;

    float4 x = *(const float4*)(p + lane * 4);
    float s = x.x + x.y + x.z + x.w;
    #pragma unroll
    for (int off = 16; off > 0; off >>= 1) s += __shfl_xor_sync(0xFFFFFFFFu, s, off);
    float mean = s * (1.0f / 128.0f);

    float dx = x.x - mean, dy = x.y - mean, dz = x.z - mean, dw = x.w - mean;
    float sq = dx * dx + dy * dy + dz * dz + dw * dw;
    #pragma unroll
    for (int off = 16; off > 0; off >>= 1) sq += __shfl_xor_sync(0xFFFFFFFFu, sq, off);
    float rstd = rsqrtf(sq * (1.0f / 128.0f) + 1e-5f);

    float4 gv = *(const float4*)(gg + lane * 4);
    float4 bv = *(const float4*)(bb + lane * 4);
    float4 o;
    o.x = dx * rstd * gv.x + bv.x;
    o.y = dy * rstd * gv.y + bv.y;
    o.z = dz * rstd * gv.z + bv.z;
    o.w = dw * rstd * gv.w + bv.w;
    *(float4*)(p + lane * 4) = o;
}

// ---------------- gate + blend, writes final h_n for this layer -------------
__global__ void gate_kernel(const float* __restrict__ gw, const float* __restrict__ gbp,
                            float* __restrict__ hout)
{
    int row  = blockIdx.x * 4 + (threadIdx.x >> 5);
    int lane = threadIdx.x & 31;
    const float* hn = g_hn  + (long)row * 128;
    const float* ms = g_msg + (long)row * 128;

    float4 hv = *(const float4*)(hn + lane * 4);
    float4 mv = *(const float4*)(ms + lane * 4);
    float4 w1 = *(const float4*)(gw + lane * 4);
    float4 w2 = *(const float4*)(gw + 128 + lane * 4);

    float p = hv.x * w1.x + hv.y * w1.y + hv.z * w1.z + hv.w * w1.w
            + mv.x * w2.x + mv.y * w2.y + mv.z * w2.z + mv.w * w2.w;
    #pragma unroll
    for (int off = 16; off > 0; off >>= 1) p += __shfl_xor_sync(0xFFFFFFFFu, p, off);
    float gt = sigf(p + gbp[0]);

    float4 o;
    o.x = (1.0f - gt) * hv.x + gt * mv.x;
    o.y = (1.0f - gt) * hv.y + gt * mv.y;
    o.z = (1.0f - gt) * hv.z + gt * mv.z;
    o.w = (1.0f - gt) * hv.w + gt * mv.w;
    *(float4*)(hout + (long)row * 128 + lane * 4) = o;
}

// ---------------- host orchestration ----------------------------------------
extern "C" void kernel_launch(void* const* d_in, const int* in_sizes, int n_in,
                              void* d_out, int out_size)
{
    const int*   tokens     = (const int*)  d_in[0];
    const float* h_in       = (const float*)d_in[1];
    const float* emb        = (const float*)d_in[2];
    const float* wih0_c0    = (const float*)d_in[3];
    /* d_in[4] = wih0_rest, unused by the reference math */
    const float* bih0       = (const float*)d_in[5];
    const float* whh0       = (const float*)d_in[6];
    const float* bhh0       = (const float*)d_in[7];
    const float* wih        = (const float*)d_in[8];
    const float* whh        = (const float*)d_in[9];
    const float* bih        = (const float*)d_in[10];
    const float* bhh        = (const float*)d_in[11];
    const float* attn_in_w  = (const float*)d_in[12];
    const float* attn_in_b  = (const float*)d_in[13];
    const float* attn_out_w = (const float*)d_in[14];
    const float* attn_out_b = (const float*)d_in[15];
    const float* ln_g       = (const float*)d_in[16];
    const float* ln_b       = (const float*)d_in[17];
    const float* gate_w     = (const float*)d_in[18];
    const float* gate_b     = (const float*)d_in[19];
    const float* head_w     = (const float*)d_in[20];
    const float* head_b     = (const float*)d_in[21];

    float* yOut = (float*)d_out;                       // (B, O)
    float* hOut = yOut + (size_t)Bsz * Oo;             // (L, C, B, H)

    float *px0, *pgi, *pgh, *pqkv, *phn, *patt, *pmsg;
    cudaGetSymbolAddress((void**)&px0,  g_x0);
    cudaGetSymbolAddress((void**)&pgi,  g_gi);
    cudaGetSymbolAddress((void**)&pgh,  g_gh);
    cudaGetSymbolAddress((void**)&pqkv, g_qkv);
    cudaGetSymbolAddress((void**)&phn,  g_hn);
    cudaGetSymbolAddress((void**)&patt, g_att);
    cudaGetSymbolAddress((void**)&pmsg, g_msg);

    cudaFuncSetAttribute(gemm_tc, cudaFuncAttributeMaxDynamicSharedMemorySize, SM_TOT);

    const long CBH = (long)Cc * Bsz * Hd;
    (void)in_sizes; (void)n_in; (void)out_size;

    dim3 gB(Bsz / 128, G3H / 128, Cc);     // 3H-output GEMMs, all cells
    dim3 gO(Bsz / 128, Hd  / 128, Cc);     // H-output GEMM (out proj)

    for (int l = 0; l < Ll; l++) {
        const float* hl = h_in + (size_t)l * CBH;

        // ---- gi ----
        if (l == 0) {
            gather_x0<<<(Bsz * 32) / 256, 256>>>(tokens, emb);
            dim3 g1(Bsz / 128, G3H / 128, 1);
            gemm_tc<<<g1, 256, SM_TOT>>>(px0, wih0_c0, bih0, pgi, G3H, 0, 0, 0, 0);
            fill_gi0<<<(3 * Bsz * 96) / 256, 256>>>(bih0);
        } else {
            gemm_tc<<<gB, 256, SM_TOT>>>(hOut + (size_t)(l - 1) * CBH,
                                         wih + (size_t)(l - 1) * Cc * G3H * Hd,
                                         bih + (size_t)(l - 1) * Cc * G3H,
                                         pgi, G3H,
                                         (long)Bsz * Hd, (long)G3H * Hd, G3H, (long)Bsz * G3H);
        }

        // ---- gh ----
        const float* whh_l = (l == 0) ? whh0 : whh + (size_t)(l - 1) * Cc * G3H * Hd;
        const float* bhh_l = (l == 0) ? bhh0 : bhh + (size_t)(l - 1) * Cc * G3H;
        gemm_tc<<<gB, 256, SM_TOT>>>(hl, whh_l, bhh_l, pgh, G3H,
                                     (long)Bsz * Hd, (long)G3H * Hd, G3H, (long)Bsz * G3H);

        // ---- GRU ----
        gru_kernel<<<((long)Cc * Bsz * 32) / 256, 256>>>(hl);

        // ---- QKV (weights shared across cells: strides 0) ----
        gemm_tc<<<gB, 256, SM_TOT>>>(phn,
                                     attn_in_w + (size_t)l * G3H * Hd,
                                     attn_in_b + (size_t)l * G3H,
                                     pqkv, G3H,
                                     (long)Bsz * Hd, 0, 0, (long)Bsz * G3H);

        // ---- attention over 4 cells ----
        attn_kernel<<<(Bsz * NHh) / 4, 128>>>();

        // ---- out projection ----
        gemm_tc<<<gO, 256, SM_TOT>>>(patt,
                                     attn_out_w + (size_t)l * Hd * Hd,
                                     attn_out_b + (size_t)l * Hd,
                                     pmsg, Hd,
                                     (long)Bsz * Hd, 0, 0, (long)Bsz * Hd);

        // ---- LayerNorm (in place on g_msg) ----
        ln_kernel<<<(Cc * Bsz) / 4, 128>>>(ln_g + (size_t)l * Hd, ln_b + (size_t)l * Hd);

        // ---- gate + blend -> h_n[l] ----
        gate_kernel<<<(Cc * Bsz) / 4, 128>>>(gate_w + (size_t)l * 2 * Hd,
                                             gate_b + l,
                                             hOut + (size_t)l * CBH);
    }

    // ---- head: y = h_n[L-1, 0] @ head_w.T + head_b ----
    dim3 gH(Bsz / 128, Oo / 128, 1);
    gemm_tc<<<gH, 256, SM_TOT>>>(hOut + (size_t)(Ll - 1) * CBH, head_w, head_b,
                                 yOut, Oo, 0, 0, 0, 0);
}

// round 5
// speedup vs baseline: 1.8223x; 1.1786x over previous
#include <cuda_runtime.h>
#include <cuda_bf16.h>
#include <math.h>
#include <stdint.h>

#define Bsz 16384
#define Hd  128
#define Cc  4
#define Ll  6
#define NHh 4
#define HDd 32
#define Oo  1024
#define G3H 384

// ---------------- scratch (static device globals; no allocations) ----------
__device__ float g_x0 [(size_t)Bsz * Hd];
__device__ float g_gi [(size_t)Cc * Bsz * G3H];
__device__ float g_gh [(size_t)Cc * Bsz * G3H];
__device__ float g_qkv[(size_t)Cc * Bsz * G3H];
__device__ float g_hn [(size_t)Cc * Bsz * Hd];
__device__ float g_att[(size_t)Cc * Bsz * Hd];
__device__ float g_msg[(size_t)Cc * Bsz * Hd];

__device__ __forceinline__ float sigf(float x) { return 1.0f / (1.0f + expf(-x)); }

// ======================= HMMA (mma.sync) GEMM =======================
// Y[c,b,g] = sum_k X[c,b,k] * W[c,g,k] + bias[c,g],  K = 128 fixed.
// CTA tile: 128(b) x 64(g). 8 warps (4 m-sub x 2 n-sub), warp tile 32(m) x 32(n).
// fp32 operands split into bf16 hi+lo; D = Ah*Bh + Ah*Bl + Al*Bh (fp32 accum).
// smem = 104.4KB -> 2 CTAs/SM: one CTA's fill overlaps the other's mainloop.

#define KPAD    136                 // 128 + 8 bf16 padding (272B row stride)
#define ROWB    (KPAD * 2)          // 272 bytes per row
#define TILE_A  ((size_t)128 * ROWB)  // 34816
#define TILE_Bt ((size_t)64  * ROWB)  // 17408
#define SM_AH   0
#define SM_AL   (SM_AH + TILE_A)
#define SM_BH   (SM_AL + TILE_A)
#define SM_BL   (SM_BH + TILE_Bt)
#define SM_TOT  (SM_BL + TILE_Bt)   // 104448 bytes

__device__ __forceinline__ uint32_t smem_u32(const void* p) {
    uint32_t a;
    asm("{ .reg .u64 t; cvta.to.shared.u64 t, %1; cvt.u32.u64 %0, t; }" : "=r"(a) : "l"(p));
    return a;
}

__device__ __forceinline__ uint32_t pack_bf16(__nv_bfloat16 a, __nv_bfloat16 b) {
    __nv_bfloat162 t = __nv_bfloat162(a, b);
    return *reinterpret_cast<uint32_t*>(&t);
}

__device__ __forceinline__ void mma16816(float* c, const uint32_t* a, const uint32_t* b) {
    asm volatile(
        "mma.sync.aligned.m16n8k16.row.col.f32.bf16.bf16.f32 "
        "{%0,%1,%2,%3}, {%4,%5,%6,%7}, {%8,%9}, {%0,%1,%2,%3};\n"
        : "+f"(c[0]), "+f"(c[1]), "+f"(c[2]), "+f"(c[3])
        : "r"(a[0]), "r"(a[1]), "r"(a[2]), "r"(a[3]), "r"(b[0]), "r"(b[1]));
}

#define LDSM_X4(r0, r1, r2, r3, addr) \
    asm volatile("ldmatrix.sync.aligned.m8n8.x4.shared.b16 {%0,%1,%2,%3}, [%4];" \
                 : "=r"(r0), "=r"(r1), "=r"(r2), "=r"(r3) : "r"(addr))

struct Frags {
    uint32_t ah[2][4];
    uint32_t al[2][4];
    uint32_t bh[4][2];
    uint32_t bl[4][2];
};

__device__ __forceinline__ void ld_frags(Frags& f, uint32_t aH, uint32_t aL,
                                         uint32_t bH, uint32_t bL) {
    #pragma unroll
    for (int i = 0; i < 2; i++)
        LDSM_X4(f.ah[i][0], f.ah[i][1], f.ah[i][2], f.ah[i][3], aH + i * (16 * ROWB));
    #pragma unroll
    for (int i = 0; i < 2; i++)
        LDSM_X4(f.al[i][0], f.al[i][1], f.al[i][2], f.al[i][3], aL + i * (16 * ROWB));
    LDSM_X4(f.bh[0][0], f.bh[0][1], f.bh[1][0], f.bh[1][1], bH);
    LDSM_X4(f.bh[2][0], f.bh[2][1], f.bh[3][0], f.bh[3][1], bH + 16 * ROWB);
    LDSM_X4(f.bl[0][0], f.bl[0][1], f.bl[1][0], f.bl[1][1], bL);
    LDSM_X4(f.bl[2][0], f.bl[2][1], f.bl[3][0], f.bl[3][1], bL + 16 * ROWB);
}

// Load nrows x 128 f32 tile (row stride 128) -> bf16 hi/lo SMEM tiles (k-padded).
__device__ __forceinline__ void fill_split(const float* __restrict__ g,
                                           char* smem, int off_hi, int off_lo,
                                           int tid, int nrows) {
    int total = nrows * 32;
    #pragma unroll 4
    for (int idx = tid; idx < total; idx += 256) {
        int row = idx >> 5;
        int c4  = idx & 31;
        float4 v = *reinterpret_cast<const float4*>(g + (long)row * 128 + c4 * 4);

        __nv_bfloat16 h0 = __float2bfloat16(v.x);
        __nv_bfloat16 h1 = __float2bfloat16(v.y);
        __nv_bfloat16 h2 = __float2bfloat16(v.z);
        __nv_bfloat16 h3 = __float2bfloat16(v.w);
        __nv_bfloat16 l0 = __float2bfloat16(v.x - __bfloat162float(h0));
        __nv_bfloat16 l1 = __float2bfloat16(v.y - __bfloat162float(h1));
        __nv_bfloat16 l2 = __float2bfloat16(v.z - __bfloat162float(h2));
        __nv_bfloat16 l3 = __float2bfloat16(v.w - __bfloat162float(h3));

        int boff = row * ROWB + c4 * 8;   // bytes
        *reinterpret_cast<uint2*>(smem + off_hi + boff) =
            make_uint2(pack_bf16(h0, h1), pack_bf16(h2, h3));
        *reinterpret_cast<uint2*>(smem + off_lo + boff) =
            make_uint2(pack_bf16(l0, l1), pack_bf16(l2, l3));
    }
}

__global__ __launch_bounds__(256, 2) void gemm_tc(
    const float* __restrict__ X, const float* __restrict__ W,
    const float* __restrict__ bias, float* __restrict__ Y,
    int G, long xStride, long wStride, long bStride, long yStride)
{
    extern __shared__ char smem[];

    int c = blockIdx.z;
    X    += (long)c * xStride;
    W    += (long)c * wStride;
    bias += (long)c * bStride;
    Y    += (long)c * yStride;

    int b0   = blockIdx.x * 128;
    int g0   = blockIdx.y * 64;
    int tid  = threadIdx.x;
    int wid  = tid >> 5;
    int lane = tid & 31;

    fill_split(X + (long)b0 * 128, smem, SM_AH, SM_AL, tid, 128);
    fill_split(W + (long)g0 * 128, smem, SM_BH, SM_BL, tid, 64);
    __syncthreads();

    int wm = (wid & 3) * 32;    // warp m offset within CTA tile
    int wn = (wid >> 2) * 32;   // warp n offset

    uint32_t sbase = smem_u32(smem);
    int a_lane = (wm + (lane & 7) + ((lane >> 3) & 1) * 8) * ROWB + (lane >> 4) * 16;
    int b_lane = (wn + (lane & 7) + ((lane >> 4) & 1) * 8) * ROWB + ((lane >> 3) & 1) * 16;

    uint32_t aH = sbase + SM_AH + a_lane;
    uint32_t aL = sbase + SM_AL + a_lane;
    uint32_t bH = sbase + SM_BH + b_lane;
    uint32_t bL = sbase + SM_BL + b_lane;

    float acc[2][4][4];
    #pragma unroll
    for (int i = 0; i < 2; i++)
        #pragma unroll
        for (int j = 0; j < 4; j++)
            #pragma unroll
            for (int r = 0; r < 4; r++) acc[i][j][r] = 0.0f;

    Frags fr[2];
    ld_frags(fr[0], aH, aL, bH, bL);

    #pragma unroll
    for (int kk = 0; kk < 8; kk++) {
        if (kk < 7) {
            int ko = (kk + 1) * 32;   // 16 bf16 = 32 bytes per k-step
            ld_frags(fr[(kk + 1) & 1], aH + ko, aL + ko, bH + ko, bL + ko);
        }
        Frags& f = fr[kk & 1];
        #pragma unroll
        for (int i = 0; i < 2; i++)
            #pragma unroll
            for (int j = 0; j < 4; j++) {
                mma16816(acc[i][j], f.ah[i], f.bh[j]);
                mma16816(acc[i][j], f.ah[i], f.bl[j]);
                mma16816(acc[i][j], f.al[i], f.bh[j]);
            }
    }

    // epilogue: c0,c1 -> (row, col..col+1); c2,c3 -> (row+8, col..col+1)
    int colb = g0 + wn + (lane & 3) * 2;
    #pragma unroll
    for (int i = 0; i < 2; i++) {
        int row = b0 + wm + i * 16 + (lane >> 2);
        #pragma unroll
        for (int j = 0; j < 4; j++) {
            int col = colb + j * 8;
            float bx = bias[col], by = bias[col + 1];
            float2 o0 = make_float2(acc[i][j][0] + bx, acc[i][j][1] + by);
            float2 o1 = make_float2(acc[i][j][2] + bx, acc[i][j][3] + by);
            *reinterpret_cast<float2*>(Y + (long)row * G + col)       = o0;
            *reinterpret_cast<float2*>(Y + (long)(row + 8) * G + col) = o1;
        }
    }
}

// ---------------- embedding gather: x0[b,:] = emb[tokens[b],:] --------------
__global__ void gather_x0(const int* __restrict__ tok, const float* __restrict__ emb)
{
    long t = (long)blockIdx.x * 256 + threadIdx.x;   // B*32 threads
    int b  = (int)(t >> 5);
    int e4 = (int)(t & 31) << 2;
    float4 v = *(const float4*)(emb + (long)tok[b] * 128 + e4);
    *(float4*)(g_x0 + (long)b * 128 + e4) = v;
}

// ---------------- l=0 cells 1..3: gi = bias broadcast -----------------------
__global__ void fill_gi0(const float* __restrict__ bih0)
{
    long t = (long)blockIdx.x * 256 + threadIdx.x;   // 3*B*96 float4 units
    int  g4  = (int)(t % 96) * 4;
    long rem = t / 96;
    int  b   = (int)(rem % Bsz);
    int  c   = 1 + (int)(rem / Bsz);
    float4 v = *(const float4*)(bih0 + (long)c * G3H + g4);
    *(float4*)(g_gi + ((long)c * Bsz + b) * G3H + g4) = v;
}

// ---------------- GRU elementwise -------------------------------------------
__global__ void gru_kernel(const float* __restrict__ hprev)
{
    long t   = (long)blockIdx.x * 256 + threadIdx.x;   // C*B*32
    long row = t >> 5;
    int  h4  = (int)(t & 31) << 2;
    const float* gi = g_gi + row * G3H;
    const float* gh = g_gh + row * G3H;

    float4 ir  = *(const float4*)(gi + h4);
    float4 iz  = *(const float4*)(gi + 128 + h4);
    float4 inn = *(const float4*)(gi + 256 + h4);
    float4 hr  = *(const float4*)(gh + h4);
    float4 hz  = *(const float4*)(gh + 128 + h4);
    float4 hnn = *(const float4*)(gh + 256 + h4);
    float4 hp  = *(const float4*)(hprev + row * 128 + h4);

    float4 out;
    {
        float r = sigf(ir.x + hr.x), z = sigf(iz.x + hz.x);
        float n = tanhf(inn.x + r * hnn.x);
        out.x = (1.0f - z) * n + z * hp.x;
    }
    {
        float r = sigf(ir.y + hr.y), z = sigf(iz.y + hz.y);
        float n = tanhf(inn.y + r * hnn.y);
        out.y = (1.0f - z) * n + z * hp.y;
    }
    {
        float r = sigf(ir.z + hr.z), z = sigf(iz.z + hz.z);
        float n = tanhf(inn.z + r * hnn.z);
        out.z = (1.0f - z) * n + z * hp.z;
    }
    {
        float r = sigf(ir.w + hr.w), z = sigf(iz.w + hz.w);
        float n = tanhf(inn.w + r * hnn.w);
        out.w = (1.0f - z) * n + z * hp.w;
    }
    *(float4*)(g_hn + row * 128 + h4) = out;
}

// ---------------- tiny attention over C=4 positions --------------------------
__global__ void attn_kernel()
{
    int gw   = blockIdx.x * 4 + (threadIdx.x >> 5);   // (b, nh) index
    int lane = threadIdx.x & 31;                      // = head dim
    int b  = gw >> 2;
    int nh = gw & 3;

    float q[4], k[4], v[4];
    #pragma unroll
    for (int c = 0; c < 4; c++) {
        const float* p = g_qkv + ((long)c * Bsz + b) * G3H + nh * 32 + lane;
        q[c] = p[0];
        k[c] = p[128];
        v[c] = p[256];
    }

    float s[4][4];
    #pragma unroll
    for (int qc = 0; qc < 4; qc++) {
        #pragma unroll
        for (int kc = 0; kc < 4; kc++) {
            float p = q[qc] * k[kc];
            #pragma unroll
            for (int off = 16; off > 0; off >>= 1)
                p += __shfl_xor_sync(0xFFFFFFFFu, p, off);
            s[qc][kc] = p * 0.17677669529663687f;   // 1/sqrt(32)
        }
    }

    #pragma unroll
    for (int qc = 0; qc < 4; qc++) {
        float m = fmaxf(fmaxf(s[qc][0], s[qc][1]), fmaxf(s[qc][2], s[qc][3]));
        float e0 = expf(s[qc][0] - m), e1 = expf(s[qc][1] - m);
        float e2 = expf(s[qc][2] - m), e3 = expf(s[qc][3] - m);
        float inv = 1.0f / (e0 + e1 + e2 + e3);
        float o = (e0 * v[0] + e1 * v[1] + e2 * v[2] + e3 * v[3]) * inv;
        g_att[((long)qc * Bsz + b) * 128 + nh * 32 + lane] = o;
    }
}

// ---------------- LayerNorm over H=128 (in place on g_msg) ------------------
__global__ void ln_kernel(const float* __restrict__ gg, const float* __restrict__ bb)
{
    int row  = blockIdx.x * 4 + (threadIdx.x >> 5);
    int lane = threadIdx.x & 31;
    float* p = g_msg + (long)row * 128;

    float4 x = *(const float4*)(p + lane * 4);
    float s = x.x + x.y + x.z + x.w;
    #pragma unroll
    for (int off = 16; off > 0; off >>= 1) s += __shfl_xor_sync(0xFFFFFFFFu, s, off);
    float mean = s * (1.0f / 128.0f);

    float dx = x.x - mean, dy = x.y - mean, dz = x.z - mean, dw = x.w - mean;
    float sq = dx * dx + dy * dy + dz * dz + dw * dw;
    #pragma unroll
    for (int off = 16; off > 0; off >>= 1) sq += __shfl_xor_sync(0xFFFFFFFFu, sq, off);
    float rstd = rsqrtf(sq * (1.0f / 128.0f) + 1e-5f);

    float4 gv = *(const float4*)(gg + lane * 4);
    float4 bv = *(const float4*)(bb + lane * 4);
    float4 o;
    o.x = dx * rstd * gv.x + bv.x;
    o.y = dy * rstd * gv.y + bv.y;
    o.z = dz * rstd * gv.z + bv.z;
    o.w = dw * rstd * gv.w + bv.w;
    *(float4*)(p + lane * 4) = o;
}

// ---------------- gate + blend, writes final h_n for this layer -------------
__global__ void gate_kernel(const float* __restrict__ gw, const float* __restrict__ gbp,
                            float* __restrict__ hout)
{
    int row  = blockIdx.x * 4 + (threadIdx.x >> 5);
    int lane = threadIdx.x & 31;
    const float* hn = g_hn  + (long)row * 128;
    const float* ms = g_msg + (long)row * 128;

    float4 hv = *(const float4*)(hn + lane * 4);
    float4 mv = *(const float4*)(ms + lane * 4);
    float4 w1 = *(const float4*)(gw + lane * 4);
    float4 w2 = *(const float4*)(gw + 128 + lane * 4);

    float p = hv.x * w1.x + hv.y * w1.y + hv.z * w1.z + hv.w * w1.w
            + mv.x * w2.x + mv.y * w2.y + mv.z * w2.z + mv.w * w2.w;
    #pragma unroll
    for (int off = 16; off > 0; off >>= 1) p += __shfl_xor_sync(0xFFFFFFFFu, p, off);
    float gt = sigf(p + gbp[0]);

    float4 o;
    o.x = (1.0f - gt) * hv.x + gt * mv.x;
    o.y = (1.0f - gt) * hv.y + gt * mv.y;
    o.z = (1.0f - gt) * hv.z + gt * mv.z;
    o.w = (1.0f - gt) * hv.w + gt * mv.w;
    *(float4*)(hout + (long)row * 128 + lane * 4) = o;
}

// ---------------- host orchestration ----------------------------------------
extern "C" void kernel_launch(void* const* d_in, const int* in_sizes, int n_in,
                              void* d_out, int out_size)
{
    const int*   tokens     = (const int*)  d_in[0];
    const float* h_in       = (const float*)d_in[1];
    const float* emb        = (const float*)d_in[2];
    const float* wih0_c0    = (const float*)d_in[3];
    /* d_in[4] = wih0_rest, unused by the reference math */
    const float* bih0       = (const float*)d_in[5];
    const float* whh0       = (const float*)d_in[6];
    const float* bhh0       = (const float*)d_in[7];
    const float* wih        = (const float*)d_in[8];
    const float* whh        = (const float*)d_in[9];
    const float* bih        = (const float*)d_in[10];
    const float* bhh        = (const float*)d_in[11];
    const float* attn_in_w  = (const float*)d_in[12];
    const float* attn_in_b  = (const float*)d_in[13];
    const float* attn_out_w = (const float*)d_in[14];
    const float* attn_out_b = (const float*)d_in[15];
    const float* ln_g       = (const float*)d_in[16];
    const float* ln_b       = (const float*)d_in[17];
    const float* gate_w     = (const float*)d_in[18];
    const float* gate_b     = (const float*)d_in[19];
    const float* head_w     = (const float*)d_in[20];
    const float* head_b     = (const float*)d_in[21];

    float* yOut = (float*)d_out;                       // (B, O)
    float* hOut = yOut + (size_t)Bsz * Oo;             // (L, C, B, H)

    float *px0, *pgi, *pgh, *pqkv, *phn, *patt, *pmsg;
    cudaGetSymbolAddress((void**)&px0,  g_x0);
    cudaGetSymbolAddress((void**)&pgi,  g_gi);
    cudaGetSymbolAddress((void**)&pgh,  g_gh);
    cudaGetSymbolAddress((void**)&pqkv, g_qkv);
    cudaGetSymbolAddress((void**)&phn,  g_hn);
    cudaGetSymbolAddress((void**)&patt, g_att);
    cudaGetSymbolAddress((void**)&pmsg, g_msg);

    cudaFuncSetAttribute(gemm_tc, cudaFuncAttributeMaxDynamicSharedMemorySize, SM_TOT);

    const long CBH = (long)Cc * Bsz * Hd;
    (void)in_sizes; (void)n_in; (void)out_size;

    dim3 gB(Bsz / 128, G3H / 64, Cc);     // 3H-output GEMMs, all cells
    dim3 gO(Bsz / 128, Hd  / 64, Cc);     // H-output GEMM (out proj)

    for (int l = 0; l < Ll; l++) {
        const float* hl = h_in + (size_t)l * CBH;

        // ---- gi ----
        if (l == 0) {
            gather_x0<<<(Bsz * 32) / 256, 256>>>(tokens, emb);
            dim3 g1(Bsz / 128, G3H / 64, 1);
            gemm_tc<<<g1, 256, SM_TOT>>>(px0, wih0_c0, bih0, pgi, G3H, 0, 0, 0, 0);
            fill_gi0<<<(3 * Bsz * 96) / 256, 256>>>(bih0);
        } else {
            gemm_tc<<<gB, 256, SM_TOT>>>(hOut + (size_t)(l - 1) * CBH,
                                         wih + (size_t)(l - 1) * Cc * G3H * Hd,
                                         bih + (size_t)(l - 1) * Cc * G3H,
                                         pgi, G3H,
                                         (long)Bsz * Hd, (long)G3H * Hd, G3H, (long)Bsz * G3H);
        }

        // ---- gh ----
        const float* whh_l = (l == 0) ? whh0 : whh + (size_t)(l - 1) * Cc * G3H * Hd;
        const float* bhh_l = (l == 0) ? bhh0 : bhh + (size_t)(l - 1) * Cc * G3H;
        gemm_tc<<<gB, 256, SM_TOT>>>(hl, whh_l, bhh_l, pgh, G3H,
                                     (long)Bsz * Hd, (long)G3H * Hd, G3H, (long)Bsz * G3H);

        // ---- GRU ----
        gru_kernel<<<((long)Cc * Bsz * 32) / 256, 256>>>(hl);

        // ---- QKV (weights shared across cells: strides 0) ----
        gemm_tc<<<gB, 256, SM_TOT>>>(phn,
                                     attn_in_w + (size_t)l * G3H * Hd,
                                     attn_in_b + (size_t)l * G3H,
                                     pqkv, G3H,
                                     (long)Bsz * Hd, 0, 0, (long)Bsz * G3H);

        // ---- attention over 4 cells ----
        attn_kernel<<<(Bsz * NHh) / 4, 128>>>();

        // ---- out projection ----
        gemm_tc<<<gO, 256, SM_TOT>>>(patt,
                                     attn_out_w + (size_t)l * Hd * Hd,
                                     attn_out_b + (size_t)l * Hd,
                                     pmsg, Hd,
                                     (long)Bsz * Hd, 0, 0, (long)Bsz * Hd);

        // ---- LayerNorm (in place on g_msg) ----
        ln_kernel<<<(Cc * Bsz) / 4, 128>>>(ln_g + (size_t)l * Hd, ln_b + (size_t)l * Hd);

        // ---- gate + blend -> h_n[l] ----
        gate_kernel<<<(Cc * Bsz) / 4, 128>>>(gate_w + (size_t)l * 2 * Hd,
                                             gate_b + l,
                                             hOut + (size_t)l * CBH);
    }

    // ---- head: y = h_n[L-1, 0] @ head_w.T + head_b ----
    dim3 gH(Bsz / 128, Oo / 64, 1);
    gemm_tc<<<gH, 256, SM_TOT>>>(hOut + (size_t)(Ll - 1) * CBH, head_w, head_b,
                                 yOut, Oo, 0, 0, 0, 0);
}

// round 6
// speedup vs baseline: 1.9113x; 1.0489x over previous
#include <cuda_runtime.h>
#include <cuda_bf16.h>
#include <math.h>
#include <stdint.h>

#define Bsz 16384
#define Hd  128
#define Cc  4
#define Ll  6
#define NHh 4
#define HDd 32
#define Oo  1024
#define G3H 384

// ---------------- fp32 scratch ----------------------------------------------
__device__ __align__(256) float g_gi [(size_t)Cc * Bsz * G3H];
__device__ __align__(256) float g_gh [(size_t)Cc * Bsz * G3H];
__device__ __align__(256) float g_qkv[(size_t)Cc * Bsz * G3H];
__device__ __align__(256) float g_hn [(size_t)Cc * Bsz * Hd];
__device__ __align__(256) float g_msg[(size_t)Cc * Bsz * Hd];

// ---------------- bf16 hi/lo split buffers ----------------------------------
__device__ __align__(256) __nv_bfloat16 g_x0h[(size_t)Bsz * Hd];
__device__ __align__(256) __nv_bfloat16 g_x0l[(size_t)Bsz * Hd];
__device__ __align__(256) __nv_bfloat16 g_hh [(size_t)Ll * Cc * Bsz * Hd];  // h_in split
__device__ __align__(256) __nv_bfloat16 g_hl [(size_t)Ll * Cc * Bsz * Hd];
__device__ __align__(256) __nv_bfloat16 g_nh [(size_t)Cc * Bsz * Hd];       // hn split
__device__ __align__(256) __nv_bfloat16 g_nl [(size_t)Cc * Bsz * Hd];
__device__ __align__(256) __nv_bfloat16 g_aah[(size_t)Cc * Bsz * Hd];       // att split
__device__ __align__(256) __nv_bfloat16 g_aal[(size_t)Cc * Bsz * Hd];
__device__ __align__(256) __nv_bfloat16 g_ph [(size_t)Cc * Bsz * Hd];       // hOut split
__device__ __align__(256) __nv_bfloat16 g_pl [(size_t)Cc * Bsz * Hd];
// weights
__device__ __align__(256) __nv_bfloat16 g_wih0h[(size_t)G3H * Hd];
__device__ __align__(256) __nv_bfloat16 g_wih0l[(size_t)G3H * Hd];
__device__ __align__(256) __nv_bfloat16 g_whh0h[(size_t)Cc * G3H * Hd];
__device__ __align__(256) __nv_bfloat16 g_whh0l[(size_t)Cc * G3H * Hd];
__device__ __align__(256) __nv_bfloat16 g_wihh[(size_t)(Ll-1) * Cc * G3H * Hd];
__device__ __align__(256) __nv_bfloat16 g_wihl[(size_t)(Ll-1) * Cc * G3H * Hd];
__device__ __align__(256) __nv_bfloat16 g_whhh[(size_t)(Ll-1) * Cc * G3H * Hd];
__device__ __align__(256) __nv_bfloat16 g_whhl[(size_t)(Ll-1) * Cc * G3H * Hd];
__device__ __align__(256) __nv_bfloat16 g_aiwh[(size_t)Ll * G3H * Hd];
__device__ __align__(256) __nv_bfloat16 g_aiwl[(size_t)Ll * G3H * Hd];
__device__ __align__(256) __nv_bfloat16 g_aowh[(size_t)Ll * Hd * Hd];
__device__ __align__(256) __nv_bfloat16 g_aowl[(size_t)Ll * Hd * Hd];
__device__ __align__(256) __nv_bfloat16 g_hwh [(size_t)Oo * Hd];
__device__ __align__(256) __nv_bfloat16 g_hwl [(size_t)Oo * Hd];

__device__ __forceinline__ float sigf(float x) { return 1.0f / (1.0f + expf(-x)); }

__device__ __forceinline__ uint32_t pack_bf16(__nv_bfloat16 a, __nv_bfloat16 b) {
    __nv_bfloat162 t = __nv_bfloat162(a, b);
    return *reinterpret_cast<uint32_t*>(&t);
}

// split 4 fp32 values into bf16 hi/lo at elem offset off (must be 4-aligned)
__device__ __forceinline__ void store_split4(__nv_bfloat16* ph, __nv_bfloat16* pl,
                                             long off, float4 v) {
    __nv_bfloat16 h0 = __float2bfloat16(v.x);
    __nv_bfloat16 h1 = __float2bfloat16(v.y);
    __nv_bfloat16 h2 = __float2bfloat16(v.z);
    __nv_bfloat16 h3 = __float2bfloat16(v.w);
    *reinterpret_cast<uint2*>(ph + off) =
        make_uint2(pack_bf16(h0, h1), pack_bf16(h2, h3));
    __nv_bfloat16 l0 = __float2bfloat16(v.x - __bfloat162float(h0));
    __nv_bfloat16 l1 = __float2bfloat16(v.y - __bfloat162float(h1));
    __nv_bfloat16 l2 = __float2bfloat16(v.z - __bfloat162float(h2));
    __nv_bfloat16 l3 = __float2bfloat16(v.w - __bfloat162float(h3));
    *reinterpret_cast<uint2*>(pl + off) =
        make_uint2(pack_bf16(l0, l1), pack_bf16(l2, l3));
}

// ---------------- generic fp32 -> bf16 hi/lo split pass ---------------------
__global__ void split_pair(const float* __restrict__ in, __nv_bfloat16* __restrict__ oh,
                           __nv_bfloat16* __restrict__ ol)
{
    long i = (long)blockIdx.x * 256 + threadIdx.x;   // float4 index
    float4 v = reinterpret_cast<const float4*>(in)[i];
    store_split4(oh, ol, i * 4, v);
}

// ======================= HMMA (mma.sync) GEMM =======================
// Y[c,b,g] = sum_k X[c,b,k] * W[c,g,k] + bias[c,g],  K = 128 fixed.
// CTA tile 128(b) x 64(g), 8 warps (4m x 2n), warp tile 32x32, 2 CTAs/SM.
// Operands arrive pre-split as bf16 hi/lo; fill is pure cp.async.

#define KPAD    136
#define ROWB    (KPAD * 2)            // 272 bytes per row
#define TILE_A  ((size_t)128 * ROWB)
#define TILE_Bt ((size_t)64  * ROWB)
#define SM_AH   0
#define SM_AL   (SM_AH + TILE_A)
#define SM_BH   (SM_AL + TILE_A)
#define SM_BL   (SM_BH + TILE_Bt)
#define SM_TOT  (SM_BL + TILE_Bt)     // 104448 bytes

__device__ __forceinline__ uint32_t smem_u32(const void* p) {
    uint32_t a;
    asm("{ .reg .u64 t; cvta.to.shared.u64 t, %1; cvt.u32.u64 %0, t; }" : "=r"(a) : "l"(p));
    return a;
}
__device__ __forceinline__ void cpa16(uint32_t sdst, const void* gsrc) {
    asm volatile("cp.async.cg.shared.global [%0], [%1], 16;" :: "r"(sdst), "l"(gsrc));
}

__device__ __forceinline__ void mma16816(float* c, const uint32_t* a, const uint32_t* b) {
    asm volatile(
        "mma.sync.aligned.m16n8k16.row.col.f32.bf16.bf16.f32 "
        "{%0,%1,%2,%3}, {%4,%5,%6,%7}, {%8,%9}, {%0,%1,%2,%3};\n"
        : "+f"(c[0]), "+f"(c[1]), "+f"(c[2]), "+f"(c[3])
        : "r"(a[0]), "r"(a[1]), "r"(a[2]), "r"(a[3]), "r"(b[0]), "r"(b[1]));
}

#define LDSM_X4(r0, r1, r2, r3, addr) \
    asm volatile("ldmatrix.sync.aligned.m8n8.x4.shared.b16 {%0,%1,%2,%3}, [%4];" \
                 : "=r"(r0), "=r"(r1), "=r"(r2), "=r"(r3) : "r"(addr))

struct Frags {
    uint32_t ah[2][4];
    uint32_t al[2][4];
    uint32_t bh[4][2];
    uint32_t bl[4][2];
};

__device__ __forceinline__ void ld_frags(Frags& f, uint32_t aH, uint32_t aL,
                                         uint32_t bH, uint32_t bL) {
    #pragma unroll
    for (int i = 0; i < 2; i++)
        LDSM_X4(f.ah[i][0], f.ah[i][1], f.ah[i][2], f.ah[i][3], aH + i * (16 * ROWB));
    #pragma unroll
    for (int i = 0; i < 2; i++)
        LDSM_X4(f.al[i][0], f.al[i][1], f.al[i][2], f.al[i][3], aL + i * (16 * ROWB));
    LDSM_X4(f.bh[0][0], f.bh[0][1], f.bh[1][0], f.bh[1][1], bH);
    LDSM_X4(f.bh[2][0], f.bh[2][1], f.bh[3][0], f.bh[3][1], bH + 16 * ROWB);
    LDSM_X4(f.bl[0][0], f.bl[0][1], f.bl[1][0], f.bl[1][1], bL);
    LDSM_X4(f.bl[2][0], f.bl[2][1], f.bl[3][0], f.bl[3][1], bL + 16 * ROWB);
}

__global__ __launch_bounds__(256, 2) void gemm_tc(
    const __nv_bfloat16* __restrict__ Ah, const __nv_bfloat16* __restrict__ Al,
    const __nv_bfloat16* __restrict__ Bh, const __nv_bfloat16* __restrict__ Bl,
    const float* __restrict__ bias, float* __restrict__ Y,
    int G, long xStride, long wStride, long bStride, long yStride)
{
    extern __shared__ char smem[];

    int c = blockIdx.z;
    Ah   += (long)c * xStride;
    Al   += (long)c * xStride;
    Bh   += (long)c * wStride;
    Bl   += (long)c * wStride;
    bias += (long)c * bStride;
    Y    += (long)c * yStride;

    int b0   = blockIdx.x * 128;
    int g0   = blockIdx.y * 64;
    int tid  = threadIdx.x;
    int wid  = tid >> 5;
    int lane = tid & 31;

    const __nv_bfloat16* a_h = Ah + (long)b0 * 128;
    const __nv_bfloat16* a_l = Al + (long)b0 * 128;
    const __nv_bfloat16* b_h = Bh + (long)g0 * 128;
    const __nv_bfloat16* b_l = Bl + (long)g0 * 128;

    uint32_t sb = smem_u32(smem);

    // fill: pure async 16B copies (no conversion, no register staging)
    #pragma unroll 2
    for (int idx = tid; idx < 2048; idx += 256) {          // A: 128 rows x 16 chunks
        int r = idx >> 4, k = idx & 15;
        cpa16(sb + SM_AH + r * ROWB + k * 16, a_h + (long)r * 128 + k * 8);
        cpa16(sb + SM_AL + r * ROWB + k * 16, a_l + (long)r * 128 + k * 8);
    }
    #pragma unroll 2
    for (int idx = tid; idx < 1024; idx += 256) {          // B: 64 rows x 16 chunks
        int r = idx >> 4, k = idx & 15;
        cpa16(sb + SM_BH + r * ROWB + k * 16, b_h + (long)r * 128 + k * 8);
        cpa16(sb + SM_BL + r * ROWB + k * 16, b_l + (long)r * 128 + k * 8);
    }
    asm volatile("cp.async.commit_group;\ncp.async.wait_group 0;" ::: "memory");
    __syncthreads();

    int wm = (wid & 3) * 32;
    int wn = (wid >> 2) * 32;

    int a_lane = (wm + (lane & 7) + ((lane >> 3) & 1) * 8) * ROWB + (lane >> 4) * 16;
    int b_lane = (wn + (lane & 7) + ((lane >> 4) & 1) * 8) * ROWB + ((lane >> 3) & 1) * 16;

    uint32_t aH = sb + SM_AH + a_lane;
    uint32_t aL = sb + SM_AL + a_lane;
    uint32_t bH = sb + SM_BH + b_lane;
    uint32_t bL = sb + SM_BL + b_lane;

    float acc[2][4][4];
    #pragma unroll
    for (int i = 0; i < 2; i++)
        #pragma unroll
        for (int j = 0; j < 4; j++)
            #pragma unroll
            for (int r = 0; r < 4; r++) acc[i][j][r] = 0.0f;

    Frags fr[2];
    ld_frags(fr[0], aH, aL, bH, bL);

    #pragma unroll
    for (int kk = 0; kk < 8; kk++) {
        if (kk < 7) {
            int ko = (kk + 1) * 32;
            ld_frags(fr[(kk + 1) & 1], aH + ko, aL + ko, bH + ko, bL + ko);
        }
        Frags& f = fr[kk & 1];
        #pragma unroll
        for (int i = 0; i < 2; i++)
            #pragma unroll
            for (int j = 0; j < 4; j++) {
                mma16816(acc[i][j], f.ah[i], f.bh[j]);
                mma16816(acc[i][j], f.ah[i], f.bl[j]);
                mma16816(acc[i][j], f.al[i], f.bh[j]);
            }
    }

    int colb = g0 + wn + (lane & 3) * 2;
    #pragma unroll
    for (int i = 0; i < 2; i++) {
        int row = b0 + wm + i * 16 + (lane >> 2);
        #pragma unroll
        for (int j = 0; j < 4; j++) {
            int col = colb + j * 8;
            float bx = bias[col], by = bias[col + 1];
            float2 o0 = make_float2(acc[i][j][0] + bx, acc[i][j][1] + by);
            float2 o1 = make_float2(acc[i][j][2] + bx, acc[i][j][3] + by);
            *reinterpret_cast<float2*>(Y + (long)row * G + col)       = o0;
            *reinterpret_cast<float2*>(Y + (long)(row + 8) * G + col) = o1;
        }
    }
}

// ---------------- embedding gather -> bf16 hi/lo split -----------------------
__global__ void gather_x0(const int* __restrict__ tok, const float* __restrict__ emb)
{
    long t = (long)blockIdx.x * 256 + threadIdx.x;   // B*32 threads
    int b  = (int)(t >> 5);
    int e4 = (int)(t & 31) << 2;
    float4 v = *(const float4*)(emb + (long)tok[b] * 128 + e4);
    store_split4(g_x0h, g_x0l, (long)b * 128 + e4, v);
}

// ---------------- l=0 cells 1..3: gi = bias broadcast -----------------------
__global__ void fill_gi0(const float* __restrict__ bih0)
{
    long t = (long)blockIdx.x * 256 + threadIdx.x;
    int  g4  = (int)(t % 96) * 4;
    long rem = t / 96;
    int  b   = (int)(rem % Bsz);
    int  c   = 1 + (int)(rem / Bsz);
    float4 v = *(const float4*)(bih0 + (long)c * G3H + g4);
    *(float4*)(g_gi + ((long)c * Bsz + b) * G3H + g4) = v;
}

// ---------------- GRU elementwise: writes fp32 hn + bf16 split --------------
__global__ void gru_kernel(const float* __restrict__ hprev)
{
    long t   = (long)blockIdx.x * 256 + threadIdx.x;
    long row = t >> 5;
    int  h4  = (int)(t & 31) << 2;
    const float* gi = g_gi + row * G3H;
    const float* gh = g_gh + row * G3H;

    float4 ir  = *(const float4*)(gi + h4);
    float4 iz  = *(const float4*)(gi + 128 + h4);
    float4 inn = *(const float4*)(gi + 256 + h4);
    float4 hr  = *(const float4*)(gh + h4);
    float4 hz  = *(const float4*)(gh + 128 + h4);
    float4 hnn = *(const float4*)(gh + 256 + h4);
    float4 hp  = *(const float4*)(hprev + row * 128 + h4);

    float4 out;
    {
        float r = sigf(ir.x + hr.x), z = sigf(iz.x + hz.x);
        float n = tanhf(inn.x + r * hnn.x);
        out.x = (1.0f - z) * n + z * hp.x;
    }
    {
        float r = sigf(ir.y + hr.y), z = sigf(iz.y + hz.y);
        float n = tanhf(inn.y + r * hnn.y);
        out.y = (1.0f - z) * n + z * hp.y;
    }
    {
        float r = sigf(ir.z + hr.z), z = sigf(iz.z + hz.z);
        float n = tanhf(inn.z + r * hnn.z);
        out.z = (1.0f - z) * n + z * hp.z;
    }
    {
        float r = sigf(ir.w + hr.w), z = sigf(iz.w + hz.w);
        float n = tanhf(inn.w + r * hnn.w);
        out.w = (1.0f - z) * n + z * hp.w;
    }
    long off = row * 128 + h4;
    *(float4*)(g_hn + off) = out;
    store_split4(g_nh, g_nl, off, out);
}

// ---------------- tiny attention over C=4 positions -> bf16 split ------------
__global__ void attn_kernel()
{
    int gw   = blockIdx.x * 4 + (threadIdx.x >> 5);
    int lane = threadIdx.x & 31;
    int b  = gw >> 2;
    int nh = gw & 3;

    float q[4], k[4], v[4];
    #pragma unroll
    for (int c = 0; c < 4; c++) {
        const float* p = g_qkv + ((long)c * Bsz + b) * G3H + nh * 32 + lane;
        q[c] = p[0];
        k[c] = p[128];
        v[c] = p[256];
    }

    float s[4][4];
    #pragma unroll
    for (int qc = 0; qc < 4; qc++) {
        #pragma unroll
        for (int kc = 0; kc < 4; kc++) {
            float p = q[qc] * k[kc];
            #pragma unroll
            for (int off = 16; off > 0; off >>= 1)
                p += __shfl_xor_sync(0xFFFFFFFFu, p, off);
            s[qc][kc] = p * 0.17677669529663687f;   // 1/sqrt(32)
        }
    }

    #pragma unroll
    for (int qc = 0; qc < 4; qc++) {
        float m = fmaxf(fmaxf(s[qc][0], s[qc][1]), fmaxf(s[qc][2], s[qc][3]));
        float e0 = expf(s[qc][0] - m), e1 = expf(s[qc][1] - m);
        float e2 = expf(s[qc][2] - m), e3 = expf(s[qc][3] - m);
        float inv = 1.0f / (e0 + e1 + e2 + e3);
        float o = (e0 * v[0] + e1 * v[1] + e2 * v[2] + e3 * v[3]) * inv;
        long off = ((long)qc * Bsz + b) * 128 + nh * 32 + lane;
        __nv_bfloat16 h = __float2bfloat16(o);
        g_aah[off] = h;
        g_aal[off] = __float2bfloat16(o - __bfloat162float(h));
    }
}

// ---------------- fused LayerNorm + gate + blend -----------------------------
__global__ void lngate_kernel(const float* __restrict__ gg, const float* __restrict__ bb,
                              const float* __restrict__ gw, const float* __restrict__ gbp,
                              float* __restrict__ hout)
{
    int row  = blockIdx.x * 4 + (threadIdx.x >> 5);
    int lane = threadIdx.x & 31;
    const float* mp = g_msg + (long)row * 128;
    const float* hp = g_hn  + (long)row * 128;

    float4 x = *(const float4*)(mp + lane * 4);
    float s = x.x + x.y + x.z + x.w;
    #pragma unroll
    for (int off = 16; off > 0; off >>= 1) s += __shfl_xor_sync(0xFFFFFFFFu, s, off);
    float mean = s * (1.0f / 128.0f);

    float dx = x.x - mean, dy = x.y - mean, dz = x.z - mean, dw = x.w - mean;
    float sq = dx * dx + dy * dy + dz * dz + dw * dw;
    #pragma unroll
    for (int off = 16; off > 0; off >>= 1) sq += __shfl_xor_sync(0xFFFFFFFFu, sq, off);
    float rstd = rsqrtf(sq * (1.0f / 128.0f) + 1e-5f);

    float4 gv = *(const float4*)(gg + lane * 4);
    float4 bv = *(const float4*)(bb + lane * 4);
    float4 m;
    m.x = dx * rstd * gv.x + bv.x;
    m.y = dy * rstd * gv.y + bv.y;
    m.z = dz * rstd * gv.z + bv.z;
    m.w = dw * rstd * gv.w + bv.w;

    float4 hv = *(const float4*)(hp + lane * 4);
    float4 w1 = *(const float4*)(gw + lane * 4);
    float4 w2 = *(const float4*)(gw + 128 + lane * 4);

    float p = hv.x * w1.x + hv.y * w1.y + hv.z * w1.z + hv.w * w1.w
            + m.x * w2.x + m.y * w2.y + m.z * w2.z + m.w * w2.w;
    #pragma unroll
    for (int off = 16; off > 0; off >>= 1) p += __shfl_xor_sync(0xFFFFFFFFu, p, off);
    float gt = sigf(p + gbp[0]);

    float4 o;
    o.x = (1.0f - gt) * hv.x + gt * m.x;
    o.y = (1.0f - gt) * hv.y + gt * m.y;
    o.z = (1.0f - gt) * hv.z + gt * m.z;
    o.w = (1.0f - gt) * hv.w + gt * m.w;
    long off = (long)row * 128 + lane * 4;
    *(float4*)(hout + off) = o;
    store_split4(g_ph, g_pl, off, o);
}

// ---------------- host orchestration ----------------------------------------
extern "C" void kernel_launch(void* const* d_in, const int* in_sizes, int n_in,
                              void* d_out, int out_size)
{
    const int*   tokens     = (const int*)  d_in[0];
    const float* h_in       = (const float*)d_in[1];
    const float* emb        = (const float*)d_in[2];
    const float* wih0_c0    = (const float*)d_in[3];
    const float* bih0       = (const float*)d_in[5];
    const float* whh0       = (const float*)d_in[6];
    const float* bhh0       = (const float*)d_in[7];
    const float* wih        = (const float*)d_in[8];
    const float* whh        = (const float*)d_in[9];
    const float* bih        = (const float*)d_in[10];
    const float* bhh        = (const float*)d_in[11];
    const float* attn_in_w  = (const float*)d_in[12];
    const float* attn_in_b  = (const float*)d_in[13];
    const float* attn_out_w = (const float*)d_in[14];
    const float* attn_out_b = (const float*)d_in[15];
    const float* ln_g       = (const float*)d_in[16];
    const float* ln_b       = (const float*)d_in[17];
    const float* gate_w     = (const float*)d_in[18];
    const float* gate_b     = (const float*)d_in[19];
    const float* head_w     = (const float*)d_in[20];
    const float* head_b     = (const float*)d_in[21];

    float* yOut = (float*)d_out;                       // (B, O)
    float* hOut = yOut + (size_t)Bsz * Oo;             // (L, C, B, H)

    float *pgi, *pgh, *pqkv, *pmsg;
    cudaGetSymbolAddress((void**)&pgi,  g_gi);
    cudaGetSymbolAddress((void**)&pgh,  g_gh);
    cudaGetSymbolAddress((void**)&pqkv, g_qkv);
    cudaGetSymbolAddress((void**)&pmsg, g_msg);

    __nv_bfloat16 *x0h, *x0l, *hh, *hl, *nh, *nl, *aah, *aal, *ph, *pl;
    __nv_bfloat16 *wih0h, *wih0l, *whh0h, *whh0l, *wihh, *wihl, *whhh, *whhl;
    __nv_bfloat16 *aiwh, *aiwl, *aowh, *aowl, *hwh, *hwl;
    cudaGetSymbolAddress((void**)&x0h, g_x0h);   cudaGetSymbolAddress((void**)&x0l, g_x0l);
    cudaGetSymbolAddress((void**)&hh,  g_hh);    cudaGetSymbolAddress((void**)&hl,  g_hl);
    cudaGetSymbolAddress((void**)&nh,  g_nh);    cudaGetSymbolAddress((void**)&nl,  g_nl);
    cudaGetSymbolAddress((void**)&aah, g_aah);   cudaGetSymbolAddress((void**)&aal, g_aal);
    cudaGetSymbolAddress((void**)&ph,  g_ph);    cudaGetSymbolAddress((void**)&pl,  g_pl);
    cudaGetSymbolAddress((void**)&wih0h, g_wih0h); cudaGetSymbolAddress((void**)&wih0l, g_wih0l);
    cudaGetSymbolAddress((void**)&whh0h, g_whh0h); cudaGetSymbolAddress((void**)&whh0l, g_whh0l);
    cudaGetSymbolAddress((void**)&wihh, g_wihh); cudaGetSymbolAddress((void**)&wihl, g_wihl);
    cudaGetSymbolAddress((void**)&whhh, g_whhh); cudaGetSymbolAddress((void**)&whhl, g_whhl);
    cudaGetSymbolAddress((void**)&aiwh, g_aiwh); cudaGetSymbolAddress((void**)&aiwl, g_aiwl);
    cudaGetSymbolAddress((void**)&aowh, g_aowh); cudaGetSymbolAddress((void**)&aowl, g_aowl);
    cudaGetSymbolAddress((void**)&hwh,  g_hwh);  cudaGetSymbolAddress((void**)&hwl,  g_hwl);

    cudaFuncSetAttribute(gemm_tc, cudaFuncAttributeMaxDynamicSharedMemorySize, SM_TOT);

    const long CBH = (long)Cc * Bsz * Hd;
    (void)in_sizes; (void)n_in; (void)out_size;

    // ---- prolog: split weights + h into bf16 hi/lo ----
    #define SPLIT(src, dh, dl, nelem) \
        split_pair<<<(int)((nelem) / 1024), 256>>>(src, dh, dl)
    SPLIT(wih0_c0,   wih0h, wih0l, (long)G3H * Hd);
    SPLIT(whh0,      whh0h, whh0l, (long)Cc * G3H * Hd);
    SPLIT(wih,       wihh,  wihl,  (long)(Ll-1) * Cc * G3H * Hd);
    SPLIT(whh,       whhh,  whhl,  (long)(Ll-1) * Cc * G3H * Hd);
    SPLIT(attn_in_w, aiwh,  aiwl,  (long)Ll * G3H * Hd);
    SPLIT(attn_out_w,aowh,  aowl,  (long)Ll * Hd * Hd);
    SPLIT(head_w,    hwh,   hwl,   (long)Oo * Hd);
    SPLIT(h_in,      hh,    hl,    (long)Ll * CBH);
    #undef SPLIT

    dim3 gB(Bsz / 128, G3H / 64, Cc);
    dim3 gO(Bsz / 128, Hd  / 64, Cc);

    for (int l = 0; l < Ll; l++) {
        const float* hlp = h_in + (size_t)l * CBH;

        // ---- gi ----
        if (l == 0) {
            gather_x0<<<(Bsz * 32) / 256, 256>>>(tokens, emb);
            dim3 g1(Bsz / 128, G3H / 64, 1);
            gemm_tc<<<g1, 256, SM_TOT>>>(x0h, x0l, wih0h, wih0l, bih0, pgi,
                                         G3H, 0, 0, 0, 0);
            fill_gi0<<<(3 * Bsz * 96) / 256, 256>>>(bih0);
        } else {
            gemm_tc<<<gB, 256, SM_TOT>>>(ph, pl,
                                         wihh + (size_t)(l - 1) * Cc * G3H * Hd,
                                         wihl + (size_t)(l - 1) * Cc * G3H * Hd,
                                         bih + (size_t)(l - 1) * Cc * G3H,
                                         pgi, G3H,
                                         (long)Bsz * Hd, (long)G3H * Hd, G3H, (long)Bsz * G3H);
        }

        // ---- gh ----
        const __nv_bfloat16* whh_h = (l == 0) ? whh0h : whhh + (size_t)(l - 1) * Cc * G3H * Hd;
        const __nv_bfloat16* whh_l = (l == 0) ? whh0l : whhl + (size_t)(l - 1) * Cc * G3H * Hd;
        const float* bhh_l = (l == 0) ? bhh0 : bhh + (size_t)(l - 1) * Cc * G3H;
        gemm_tc<<<gB, 256, SM_TOT>>>(hh + (size_t)l * CBH, hl + (size_t)l * CBH,
                                     whh_h, whh_l, bhh_l, pgh, G3H,
                                     (long)Bsz * Hd, (long)G3H * Hd, G3H, (long)Bsz * G3H);

        // ---- GRU (writes g_hn fp32 + g_nh/g_nl split) ----
        gru_kernel<<<((long)Cc * Bsz * 32) / 256, 256>>>(hlp);

        // ---- QKV (weights shared across cells: wStride 0) ----
        gemm_tc<<<gB, 256, SM_TOT>>>(nh, nl,
                                     aiwh + (size_t)l * G3H * Hd,
                                     aiwl + (size_t)l * G3H * Hd,
                                     attn_in_b + (size_t)l * G3H,
                                     pqkv, G3H,
                                     (long)Bsz * Hd, 0, 0, (long)Bsz * G3H);

        // ---- attention (writes g_aah/g_aal split) ----
        attn_kernel<<<(Bsz * NHh) / 4, 128>>>();

        // ---- out projection ----
        gemm_tc<<<gO, 256, SM_TOT>>>(aah, aal,
                                     aowh + (size_t)l * Hd * Hd,
                                     aowl + (size_t)l * Hd * Hd,
                                     attn_out_b + (size_t)l * Hd,
                                     pmsg, Hd,
                                     (long)Bsz * Hd, 0, 0, (long)Bsz * Hd);

        // ---- fused LN + gate + blend -> hOut + g_ph/g_pl split ----
        lngate_kernel<<<(Cc * Bsz) / 4, 128>>>(ln_g + (size_t)l * Hd, ln_b + (size_t)l * Hd,
                                               gate_w + (size_t)l * 2 * Hd, gate_b + l,
                                               hOut + (size_t)l * CBH);
    }

    // ---- head: y = h_n[L-1, 0] @ head_w.T + head_b (cell 0 = g_ph offset 0) ----
    dim3 gH(Bsz / 128, Oo / 64, 1);
    gemm_tc<<<gH, 256, SM_TOT>>>(ph, pl, hwh, hwl, head_b, yOut, Oo, 0, 0, 0, 0);
}